// round 9
// baseline (speedup 1.0000x reference)
#include <cuda_runtime.h>
#include <cuda_bf16.h>
#include <cstdint>

#define NNODES 100000
#define NP     100352            // multiple of 1024 and 128
#define H      128
#define EMAX   1600000
#define NT16   (NP / 16)
#define NTILE  (NP / 128)        // 784 GEMM tiles
#define NBLK   (NP / 1024)       // 98 scan blocks

// ---------------- device scratch ----------------
__device__ float g_X[4][(size_t)NP * H];
__device__ int   g_deg[NP];
__device__ float g_invdeg[NP];
__device__ int   g_rowstart[NP + 1];
__device__ int   g_cursor[NP];
__device__ int   g_csrsrc[EMAX];
__device__ int   g_blocksum[NBLK];
// W fragments: tgt t (0..4): addr = t*131072 + ((nt*16 + ks)*32 + lane)*16
__device__ uint8_t g_wfrag[5 * 131072];
// A fragments: [tile][ks 0..7][lane]*32B
__device__ uint8_t g_fragAgg[(size_t)NT16 * 8192];
__device__ uint8_t g_fragX[4][(size_t)NT16 * 8192];

// ---------------- bf16 hi/lo split ----------------
__device__ __forceinline__ void split2(float v0, float v1, uint32_t& ph, uint32_t& pl) {
    __nv_bfloat16 h0 = __float2bfloat16(v0), h1 = __float2bfloat16(v1);
    float r0 = v0 - __bfloat162float(h0), r1 = v1 - __bfloat162float(h1);
    __nv_bfloat16 l0 = __float2bfloat16(r0), l1 = __float2bfloat16(r1);
    ph = ((uint32_t)__bfloat16_as_ushort(h1) << 16) | (uint32_t)__bfloat16_as_ushort(h0);
    pl = ((uint32_t)__bfloat16_as_ushort(l1) << 16) | (uint32_t)__bfloat16_as_ushort(l0);
}

// ---------------- CSR build ----------------
__global__ void k_zero_deg() {
    int i = blockIdx.x * blockDim.x + threadIdx.x;
    if (i < NP) g_deg[i] = 0;
}
__global__ void k_hist(const int* __restrict__ dst, int E) {
    int i = blockIdx.x * blockDim.x + threadIdx.x;
    if (i < E) atomicAdd(&g_deg[dst[i]], 1);
}
__global__ void __launch_bounds__(1024) k_scan1() {
    __shared__ int wt[32];
    int t = threadIdx.x, lane = t & 31, wid = t >> 5;
    int i = blockIdx.x * 1024 + t;
    int v = g_deg[i];
    int x = v;
    #pragma unroll
    for (int d = 1; d < 32; d <<= 1) {
        int y = __shfl_up_sync(0xffffffffu, x, d);
        if (lane >= d) x += y;
    }
    if (lane == 31) wt[wid] = x;
    __syncthreads();
    if (wid == 0) {
        int y = wt[lane];
        #pragma unroll
        for (int d = 1; d < 32; d <<= 1) {
            int z = __shfl_up_sync(0xffffffffu, y, d);
            if (lane >= d) y += z;
        }
        wt[lane] = y;
    }
    __syncthreads();
    int off = (wid == 0) ? 0 : wt[wid - 1];
    g_rowstart[i] = off + x - v;
    if (t == 1023) g_blocksum[blockIdx.x] = off + x;
    g_invdeg[i] = 1.0f / fmaxf((float)v, 1.0f);
    g_cursor[i] = 0;
}
__global__ void k_scan2() {
    __shared__ int wt[4];
    int t = threadIdx.x, lane = t & 31, wid = t >> 5;
    int v = (t < NBLK) ? g_blocksum[t] : 0;
    int x = v;
    #pragma unroll
    for (int d = 1; d < 32; d <<= 1) {
        int y = __shfl_up_sync(0xffffffffu, x, d);
        if (lane >= d) x += y;
    }
    if (lane == 31) wt[wid] = x;
    __syncthreads();
    if (t == 0) {
        int r = 0;
        #pragma unroll
        for (int w = 0; w < 4; w++) { int tmp = wt[w]; wt[w] = r; r += tmp; }
        g_rowstart[NP] = r;
    }
    __syncthreads();
    if (t < NBLK) g_blocksum[t] = wt[wid] + x - v;
}
__global__ void k_scan3() {
    int i = blockIdx.x * blockDim.x + threadIdx.x;
    if (i < NP) g_rowstart[i] += g_blocksum[i >> 10];
}
__global__ void k_fill(const int* __restrict__ src, const int* __restrict__ dst, int E) {
    int i = blockIdx.x * blockDim.x + threadIdx.x;
    if (i < E) {
        int d = dst[i];
        int p = atomicAdd(&g_cursor[d], 1);
        g_csrsrc[g_rowstart[d] + p] = src[i];
    }
}

// ---------------- emb: float copy + frag conversion (one-time) ----------------
#define SROW 132
__global__ void __launch_bounds__(256) k_emb_frag(const float* __restrict__ emb) {
    __shared__ float s_tile[16 * SROW];
    int tid = threadIdx.x;
    int tile = blockIdx.x;
    size_t rowBase = (size_t)tile * 16;
    #pragma unroll
    for (int i = 0; i < 2; i++) {
        int idx = tid + i * 256;
        int r = idx >> 5, c4 = idx & 31;
        size_t row = rowBase + r;
        float4 v = make_float4(0.f, 0.f, 0.f, 0.f);
        if (row < (size_t)NNODES) v = ((const float4*)(emb + row * H))[c4];
        *(float4*)(s_tile + r * SROW + c4 * 4) = v;
        ((float4*)(g_X[0] + row * H))[c4] = v;
    }
    __syncthreads();
    {
        int ks = tid >> 5, lane = tid & 31;
        int g = lane >> 2, tg = lane & 3;
        const float* rA = s_tile + g * SROW;
        const float* rB = s_tile + (g + 8) * SROW;
        int c = ks * 16 + tg * 2;
        uint4 ah, al;
        split2(rA[c], rA[c + 1], ah.x, al.x);
        split2(rB[c], rB[c + 1], ah.y, al.y);
        split2(rA[c + 8], rA[c + 9], ah.z, al.z);
        split2(rB[c + 8], rB[c + 9], ah.w, al.w);
        uint4* fd = (uint4*)(g_fragX[0] + ((size_t)(tile * 8 + ks) * 32 + lane) * 32);
        fd[0] = ah; fd[1] = al;
    }
}

// ---------------- aggregation: warp/node, tile->frag via smem ----------------
__global__ void __launch_bounds__(512) k_agg(int layer) {
    __shared__ float s_tile[16 * SROW];
    int tid = threadIdx.x, w = tid >> 5, lane = tid & 31;
    int tile = blockIdx.x;
    int node = tile * 16 + w;
    const float* __restrict__ xin = g_X[layer];
    int s0 = g_rowstart[node], s1 = g_rowstart[node + 1];
    float ax = 0.f, ay = 0.f, az = 0.f, aw = 0.f;
    int j = s0;
    for (; j + 4 <= s1; j += 4) {
        int i0 = g_csrsrc[j], i1 = g_csrsrc[j + 1], i2 = g_csrsrc[j + 2], i3 = g_csrsrc[j + 3];
        float4 a = ((const float4*)(xin + (size_t)i0 * H))[lane];
        float4 b = ((const float4*)(xin + (size_t)i1 * H))[lane];
        float4 c = ((const float4*)(xin + (size_t)i2 * H))[lane];
        float4 d = ((const float4*)(xin + (size_t)i3 * H))[lane];
        ax += (a.x + b.x) + (c.x + d.x);
        ay += (a.y + b.y) + (c.y + d.y);
        az += (a.z + b.z) + (c.z + d.z);
        aw += (a.w + b.w) + (c.w + d.w);
    }
    for (; j < s1; j++) {
        int i0 = g_csrsrc[j];
        float4 a = ((const float4*)(xin + (size_t)i0 * H))[lane];
        ax += a.x; ay += a.y; az += a.z; aw += a.w;
    }
    float inv = g_invdeg[node];
    *(float4*)(s_tile + w * SROW + lane * 4) = make_float4(ax * inv, ay * inv, az * inv, aw * inv);
    __syncthreads();
    if (tid < 256) {
        int ks = tid >> 5, ln = tid & 31;
        int g = ln >> 2, tg = ln & 3;
        const float* rA = s_tile + g * SROW;
        const float* rB = s_tile + (g + 8) * SROW;
        int c = ks * 16 + tg * 2;
        uint4 ah, al;
        split2(rA[c], rA[c + 1], ah.x, al.x);
        split2(rB[c], rB[c + 1], ah.y, al.y);
        split2(rA[c + 8], rA[c + 9], ah.z, al.z);
        split2(rB[c + 8], rB[c + 9], ah.w, al.w);
        uint4* fd = (uint4*)(g_fragAgg + ((size_t)(tile * 8 + ks) * 32 + ln) * 32);
        fd[0] = ah; fd[1] = al;
    }
}

// ---------------- W fragment build ----------------
__global__ void k_conv_w(const float* __restrict__ Wl, const float* __restrict__ Wr,
                         const float* __restrict__ jkW) {
    int idx = blockIdx.x * blockDim.x + threadIdx.x;
    if (idx >= 5 * 16 * 16 * 32) return;
    int lane = idx & 31;
    int ks = (idx >> 5) & 15;
    int nt = (idx >> 9) & 15;
    int tgt = idx >> 13;
    int g = lane >> 2, tg = lane & 3;
    int n = nt * 8 + g;
    int k = ks * 16 + tg * 2;

    float v[4];
    if (tgt < 3) {
        #pragma unroll
        for (int q = 0; q < 4; q++) {
            int kk = k + (q >> 1) * 8 + (q & 1);
            v[q] = (kk < 128) ? Wl[(size_t)tgt * 16384 + n * 128 + kk]
                              : Wr[(size_t)tgt * 16384 + n * 128 + kk - 128];
        }
    } else {
        int h = tgt - 3;
        #pragma unroll
        for (int q = 0; q < 4; q++) {
            int kk = k + (q >> 1) * 8 + (q & 1);
            v[q] = jkW[(size_t)n * 512 + h * 256 + kk];
        }
    }
    uint32_t bh0, bl0, bh1, bl1;
    split2(v[0], v[1], bh0, bl0);
    split2(v[2], v[3], bh1, bl1);
    *(uint4*)(g_wfrag + (size_t)tgt * 131072 + ((size_t)((nt * 16 + ks) * 32 + lane)) * 16)
        = make_uint4(bh0, bh1, bl0, bl1);
}

// ---------------- mma helper ----------------
__device__ __forceinline__ void mma_bf16(float* c, uint4 a, uint32_t b0, uint32_t b1) {
    asm volatile(
        "mma.sync.aligned.m16n8k16.row.col.f32.bf16.bf16.f32 "
        "{%0,%1,%2,%3}, {%4,%5,%6,%7}, {%8,%9}, {%0,%1,%2,%3};"
        : "+f"(c[0]), "+f"(c[1]), "+f"(c[2]), "+f"(c[3])
        : "r"(a.x), "r"(a.y), "r"(a.z), "r"(a.w), "r"(b0), "r"(b1));
}

// ================= persistent layer GEMM (R8) =================
#define MMA_SMEM (131072 + 3 * 128 * 4)
__global__ void __launch_bounds__(256, 1) k_mma(
    int layer, const float* __restrict__ bias, const float* __restrict__ gamma,
    const float* __restrict__ beta)
{
    extern __shared__ uint8_t smem[];
    float* s_par = (float*)(smem + 131072);
    int tid = threadIdx.x, w = tid >> 5, lane = tid & 31;
    int g = lane >> 2, tg = lane & 3;

    if (tid < 128) {
        s_par[tid] = bias[tid];
        s_par[128 + tid] = gamma[tid];
        s_par[256 + tid] = beta[tid];
    }
    {
        const uint4* wsrc = (const uint4*)(g_wfrag + (size_t)layer * 131072);
        uint4* wdst = (uint4*)smem;
        #pragma unroll
        for (int i = 0; i < 32; i++) wdst[tid + i * 256] = wsrc[tid + i * 256];
    }
    __syncthreads();

    const uint8_t* fragXl = g_fragX[layer];
    const float* xin = g_X[layer];
    float* xout = g_X[layer + 1];
    uint8_t* fragout = g_fragX[layer + 1];
    bool wr_float = (layer < 2);

    for (int tb = blockIdx.x; tb < NTILE; tb += gridDim.x) {
        int mt = tb * 8 + w;
        size_t m0 = (size_t)mt * 16 + g, m1 = m0 + 8;

        float acc[16][4];
        #pragma unroll
        for (int nt = 0; nt < 16; nt++)
            #pragma unroll
            for (int q = 0; q < 4; q++) acc[nt][q] = 0.f;

        for (int ksl = 0; ksl < 16; ksl++) {
            const uint8_t* asrc = (ksl < 8) ? g_fragAgg : fragXl;
            int kloc = ksl & 7;
            const uint4* ap = (const uint4*)(asrc + ((size_t)(mt * 8 + kloc) * 32 + lane) * 32);
            uint4 ah = ap[0], al = ap[1];
            #pragma unroll
            for (int nt = 0; nt < 16; nt++) {
                uint4 b = ((const uint4*)smem)[(nt * 16 + ksl) * 32 + lane];
                mma_bf16(acc[nt], ah, b.x, b.y);
                mma_bf16(acc[nt], ah, b.z, b.w);
                mma_bf16(acc[nt], al, b.x, b.y);
            }
        }

        #pragma unroll
        for (int nt = 0; nt < 16; nt++) {
            int n0 = nt * 8 + tg * 2;
            float b0 = s_par[n0], b1 = s_par[n0 + 1];
            acc[nt][0] += b0; acc[nt][1] += b1;
            acc[nt][2] += b0; acc[nt][3] += b1;
        }
        float s0 = 0.f, q0 = 0.f, s1 = 0.f, q1 = 0.f;
        #pragma unroll
        for (int nt = 0; nt < 16; nt++) {
            s0 += acc[nt][0] + acc[nt][1];
            q0 += acc[nt][0] * acc[nt][0] + acc[nt][1] * acc[nt][1];
            s1 += acc[nt][2] + acc[nt][3];
            q1 += acc[nt][2] * acc[nt][2] + acc[nt][3] * acc[nt][3];
        }
        #pragma unroll
        for (int o = 1; o <= 2; o <<= 1) {
            s0 += __shfl_xor_sync(0xffffffffu, s0, o);
            q0 += __shfl_xor_sync(0xffffffffu, q0, o);
            s1 += __shfl_xor_sync(0xffffffffu, s1, o);
            q1 += __shfl_xor_sync(0xffffffffu, q1, o);
        }
        float mu0 = s0 * (1.0f / H), mu1 = s1 * (1.0f / H);
        float rs0 = rsqrtf(q0 * (1.0f / H) - mu0 * mu0 + 1e-5f);
        float rs1 = rsqrtf(q1 * (1.0f / H) - mu1 * mu1 + 1e-5f);

        #pragma unroll
        for (int ks2 = 0; ks2 < 8; ks2++) {
            float2 oa0, oa1, ob0, ob1;
            #pragma unroll
            for (int half = 0; half < 2; half++) {
                int nt = 2 * ks2 + half;
                int n0 = nt * 8 + tg * 2;
                float ga0 = s_par[128 + n0], ga1 = s_par[128 + n0 + 1];
                float be0 = s_par[256 + n0], be1 = s_par[256 + n0 + 1];
                float2 o0, o1;
                o0.x = fmaxf((acc[nt][0] - mu0) * rs0 * ga0 + be0, 0.f);
                o0.y = fmaxf((acc[nt][1] - mu0) * rs0 * ga1 + be1, 0.f);
                o1.x = fmaxf((acc[nt][2] - mu1) * rs1 * ga0 + be0, 0.f);
                o1.y = fmaxf((acc[nt][3] - mu1) * rs1 * ga1 + be1, 0.f);
                if (layer > 0) {
                    float2 r0 = *(const float2*)(xin + m0 * H + n0);
                    float2 r1 = *(const float2*)(xin + m1 * H + n0);
                    o0.x += r0.x; o0.y += r0.y;
                    o1.x += r1.x; o1.y += r1.y;
                }
                if (wr_float) {
                    *(float2*)(xout + m0 * H + n0) = o0;
                    *(float2*)(xout + m1 * H + n0) = o1;
                }
                if (half == 0) { oa0 = o0; oa1 = o1; }
                else           { ob0 = o0; ob1 = o1; }
            }
            uint4 ah, al;
            split2(oa0.x, oa0.y, ah.x, al.x);
            split2(oa1.x, oa1.y, ah.y, al.y);
            split2(ob0.x, ob0.y, ah.z, al.z);
            split2(ob1.x, ob1.y, ah.w, al.w);
            uint4* fd = (uint4*)(fragout + ((size_t)(mt * 8 + ks2) * 32 + lane) * 32);
            fd[0] = ah; fd[1] = al;
        }
    }
}

// ================= persistent JK: phase-outer, out as accumulator =================
#define JK_SMEM (131072 + 512)
__global__ void __launch_bounds__(256, 1) k_jk(
    const float* __restrict__ jkb, float* __restrict__ outp)
{
    extern __shared__ uint8_t smem[];
    float* s_bias = (float*)(smem + 131072);
    int tid = threadIdx.x, w = tid >> 5, lane = tid & 31;
    int g = lane >> 2, tg = lane & 3;

    if (tid < 128) s_bias[tid] = jkb[tid];

    for (int ph = 0; ph < 2; ph++) {
        __syncthreads();
        {   // load this phase's W blob once per SM
            const uint4* wsrc = (const uint4*)(g_wfrag + (size_t)(3 + ph) * 131072);
            uint4* wdst = (uint4*)smem;
            #pragma unroll
            for (int i = 0; i < 32; i++) wdst[tid + i * 256] = wsrc[tid + i * 256];
        }
        __syncthreads();

        for (int tb = blockIdx.x; tb < NTILE; tb += gridDim.x) {
            int mt = tb * 8 + w;
            size_t m0 = (size_t)mt * 16 + g, m1 = m0 + 8;

            float acc[16][4];
            #pragma unroll
            for (int nt = 0; nt < 16; nt++)
                #pragma unroll
                for (int q = 0; q < 4; q++) acc[nt][q] = 0.f;

            for (int ksl = 0; ksl < 16; ksl++) {
                const uint4* ap = (const uint4*)(g_fragX[2 * ph + (ksl >> 3)]
                                  + ((size_t)(mt * 8 + (ksl & 7)) * 32 + lane) * 32);
                uint4 ah = ap[0], al = ap[1];
                #pragma unroll
                for (int nt = 0; nt < 16; nt++) {
                    uint4 b = ((const uint4*)smem)[(nt * 16 + ksl) * 32 + lane];
                    mma_bf16(acc[nt], ah, b.x, b.y);
                    mma_bf16(acc[nt], ah, b.z, b.w);
                    mma_bf16(acc[nt], al, b.x, b.y);
                }
            }

            bool w0 = m0 < (size_t)NNODES, w1 = m1 < (size_t)NNODES;
            if (ph == 0) {
                #pragma unroll
                for (int nt = 0; nt < 16; nt++) {
                    int n0 = nt * 8 + tg * 2;
                    if (w0) *(float2*)(outp + m0 * H + n0) = make_float2(acc[nt][0], acc[nt][1]);
                    if (w1) *(float2*)(outp + m1 * H + n0) = make_float2(acc[nt][2], acc[nt][3]);
                }
            } else {
                #pragma unroll
                for (int nt = 0; nt < 16; nt++) {
                    int n0 = nt * 8 + tg * 2;
                    float b0 = s_bias[n0], b1 = s_bias[n0 + 1];
                    if (w0) {
                        float2 p = *(const float2*)(outp + m0 * H + n0);
                        *(float2*)(outp + m0 * H + n0) =
                            make_float2(p.x + acc[nt][0] + b0, p.y + acc[nt][1] + b1);
                    }
                    if (w1) {
                        float2 p = *(const float2*)(outp + m1 * H + n0);
                        *(float2*)(outp + m1 * H + n0) =
                            make_float2(p.x + acc[nt][2] + b0, p.y + acc[nt][3] + b1);
                    }
                }
            }
        }
    }
}

// ---------------- launch ----------------
extern "C" void kernel_launch(void* const* d_in, const int* in_sizes, int n_in,
                              void* d_out, int out_size) {
    const float* emb = (const float*)d_in[0];
    const float* Wl  = (const float*)d_in[1];
    const float* bl  = (const float*)d_in[2];
    const float* Wr  = (const float*)d_in[3];
    const float* lg  = (const float*)d_in[4];
    const float* lb  = (const float*)d_in[5];
    const float* jkW = (const float*)d_in[6];
    const float* jkb = (const float*)d_in[7];
    const int*   ei  = (const int*)d_in[8];
    int E = in_sizes[8] / 2;
    const int* src = ei;
    const int* dst = ei + E;
    float* out = (float*)d_out;

    cudaFuncSetAttribute(k_mma, cudaFuncAttributeMaxDynamicSharedMemorySize, MMA_SMEM);
    cudaFuncSetAttribute(k_jk,  cudaFuncAttributeMaxDynamicSharedMemorySize, JK_SMEM);

    k_zero_deg<<<(NP + 255) / 256, 256>>>();
    k_hist<<<(E + 255) / 256, 256>>>(dst, E);
    k_scan1<<<NBLK, 1024>>>();
    k_scan2<<<1, 128>>>();
    k_scan3<<<(NP + 255) / 256, 256>>>();
    k_fill<<<(E + 255) / 256, 256>>>(src, dst, E);
    k_emb_frag<<<NT16, 256>>>(emb);
    k_conv_w<<<(5 * 16 * 16 * 32 + 255) / 256, 256>>>(Wl, Wr, jkW);

    for (int l = 0; l < 3; l++) {
        k_agg<<<NT16, 512>>>(l);
        k_mma<<<148, 256, MMA_SMEM>>>(l, bl + l * H, lg + l * H, lb + l * H);
    }
    k_jk<<<148, 256, JK_SMEM>>>(jkb, out);
}

// round 12
// speedup vs baseline: 1.0754x; 1.0754x over previous
#include <cuda_runtime.h>
#include <cuda_bf16.h>
#include <cuda_fp16.h>
#include <cstdint>

#define NNODES 100000
#define NP     100352            // multiple of 1024 and 128
#define H      128
#define EMAX   1600000
#define NT16   (NP / 16)
#define NTILE  (NP / 128)        // 784 GEMM tiles
#define NBLK   (NP / 1024)       // 98 scan blocks

// ---------------- device scratch ----------------
__device__ float  g_X[4][(size_t)NP * H];
__device__ __half g_Xh[3][(size_t)NP * H];     // fp16 mirror of X0..X2 (gather source)
__device__ int    g_deg[NP];
__device__ float  g_invdeg[NP];
__device__ int    g_rowstart[NP + 1];
__device__ int    g_cursor[NP];
__device__ int    g_csrsrc[EMAX];
__device__ int    g_blocksum[NBLK];
// W fragments: tgt t (0..4): addr = t*131072 + ((nt*16 + ks)*32 + lane)*16
__device__ uint8_t g_wfrag[5 * 131072];
// A fragments: [tile][ks 0..7][lane]*32B
__device__ uint8_t g_fragAgg[(size_t)NT16 * 8192];
__device__ uint8_t g_fragX[4][(size_t)NT16 * 8192];

// ---------------- bf16 hi/lo split ----------------
__device__ __forceinline__ void split2(float v0, float v1, uint32_t& ph, uint32_t& pl) {
    __nv_bfloat16 h0 = __float2bfloat16(v0), h1 = __float2bfloat16(v1);
    float r0 = v0 - __bfloat162float(h0), r1 = v1 - __bfloat162float(h1);
    __nv_bfloat16 l0 = __float2bfloat16(r0), l1 = __float2bfloat16(r1);
    ph = ((uint32_t)__bfloat16_as_ushort(h1) << 16) | (uint32_t)__bfloat16_as_ushort(h0);
    pl = ((uint32_t)__bfloat16_as_ushort(l1) << 16) | (uint32_t)__bfloat16_as_ushort(l0);
}

// ---------------- CSR build ----------------
__global__ void k_zero_deg() {
    int i = blockIdx.x * blockDim.x + threadIdx.x;
    if (i < NP) g_deg[i] = 0;
}
__global__ void k_hist(const int* __restrict__ dst, int E) {
    int i = blockIdx.x * blockDim.x + threadIdx.x;
    if (i < E) atomicAdd(&g_deg[dst[i]], 1);
}
__global__ void __launch_bounds__(1024) k_scan1() {
    __shared__ int wt[32];
    int t = threadIdx.x, lane = t & 31, wid = t >> 5;
    int i = blockIdx.x * 1024 + t;
    int v = g_deg[i];
    int x = v;
    #pragma unroll
    for (int d = 1; d < 32; d <<= 1) {
        int y = __shfl_up_sync(0xffffffffu, x, d);
        if (lane >= d) x += y;
    }
    if (lane == 31) wt[wid] = x;
    __syncthreads();
    if (wid == 0) {
        int y = wt[lane];
        #pragma unroll
        for (int d = 1; d < 32; d <<= 1) {
            int z = __shfl_up_sync(0xffffffffu, y, d);
            if (lane >= d) y += z;
        }
        wt[lane] = y;
    }
    __syncthreads();
    int off = (wid == 0) ? 0 : wt[wid - 1];
    g_rowstart[i] = off + x - v;
    if (t == 1023) g_blocksum[blockIdx.x] = off + x;
    g_invdeg[i] = 1.0f / fmaxf((float)v, 1.0f);
    g_cursor[i] = 0;
}
__global__ void k_scan2() {
    __shared__ int wt[4];
    int t = threadIdx.x, lane = t & 31, wid = t >> 5;
    int v = (t < NBLK) ? g_blocksum[t] : 0;
    int x = v;
    #pragma unroll
    for (int d = 1; d < 32; d <<= 1) {
        int y = __shfl_up_sync(0xffffffffu, x, d);
        if (lane >= d) x += y;
    }
    if (lane == 31) wt[wid] = x;
    __syncthreads();
    if (t == 0) {
        int r = 0;
        #pragma unroll
        for (int w = 0; w < 4; w++) { int tmp = wt[w]; wt[w] = r; r += tmp; }
        g_rowstart[NP] = r;
    }
    __syncthreads();
    if (t < NBLK) g_blocksum[t] = wt[wid] + x - v;
}
__global__ void k_scan3() {
    int i = blockIdx.x * blockDim.x + threadIdx.x;
    if (i < NP) g_rowstart[i] += g_blocksum[i >> 10];
}
__global__ void k_fill(const int* __restrict__ src, const int* __restrict__ dst, int E) {
    int i = blockIdx.x * blockDim.x + threadIdx.x;
    if (i < E) {
        int d = dst[i];
        int p = atomicAdd(&g_cursor[d], 1);
        g_csrsrc[g_rowstart[d] + p] = src[i];
    }
}

// ---------------- emb: float copy + fp16 mirror + frag conversion ----------------
#define SROW 132
__global__ void __launch_bounds__(256) k_emb_frag(const float* __restrict__ emb) {
    __shared__ float s_tile[16 * SROW];
    int tid = threadIdx.x;
    int tile = blockIdx.x;
    size_t rowBase = (size_t)tile * 16;
    #pragma unroll
    for (int i = 0; i < 2; i++) {
        int idx = tid + i * 256;
        int r = idx >> 5, c4 = idx & 31;
        size_t row = rowBase + r;
        float4 v = make_float4(0.f, 0.f, 0.f, 0.f);
        if (row < (size_t)NNODES) v = ((const float4*)(emb + row * H))[c4];
        *(float4*)(s_tile + r * SROW + c4 * 4) = v;
        ((float4*)(g_X[0] + row * H))[c4] = v;
        __half2 h01 = __floats2half2_rn(v.x, v.y);
        __half2 h23 = __floats2half2_rn(v.z, v.w);
        uint2 hp = make_uint2(*(uint32_t*)&h01, *(uint32_t*)&h23);
        ((uint2*)(g_Xh[0] + row * H))[c4] = hp;
    }
    __syncthreads();
    {
        int ks = tid >> 5, lane = tid & 31;
        int g = lane >> 2, tg = lane & 3;
        const float* rA = s_tile + g * SROW;
        const float* rB = s_tile + (g + 8) * SROW;
        int c = ks * 16 + tg * 2;
        uint4 ah, al;
        split2(rA[c], rA[c + 1], ah.x, al.x);
        split2(rB[c], rB[c + 1], ah.y, al.y);
        split2(rA[c + 8], rA[c + 9], ah.z, al.z);
        split2(rB[c + 8], rB[c + 9], ah.w, al.w);
        uint4* fd = (uint4*)(g_fragX[0] + ((size_t)(tile * 8 + ks) * 32 + lane) * 32);
        fd[0] = ah; fd[1] = al;
    }
}

// ---------------- aggregation: warp/node, fp16 gather, tile->frag via smem ----------------
__device__ __forceinline__ void acc_h4(uint2 u, float& a0, float& a1, float& a2, float& a3) {
    float2 f01 = __half22float2(*(__half2*)&u.x);
    float2 f23 = __half22float2(*(__half2*)&u.y);
    a0 += f01.x; a1 += f01.y; a2 += f23.x; a3 += f23.y;
}
__global__ void __launch_bounds__(512) k_agg(int layer) {
    __shared__ float s_tile[16 * SROW];
    int tid = threadIdx.x, w = tid >> 5, lane = tid & 31;
    int tile = blockIdx.x;
    int node = tile * 16 + w;
    const __half* __restrict__ xin = g_Xh[layer];
    int s0 = g_rowstart[node], s1 = g_rowstart[node + 1];
    float ax = 0.f, ay = 0.f, az = 0.f, aw = 0.f;
    int j = s0;
    for (; j + 4 <= s1; j += 4) {
        int i0 = g_csrsrc[j], i1 = g_csrsrc[j + 1], i2 = g_csrsrc[j + 2], i3 = g_csrsrc[j + 3];
        uint2 a = ((const uint2*)(xin + (size_t)i0 * H))[lane];
        uint2 b = ((const uint2*)(xin + (size_t)i1 * H))[lane];
        uint2 c = ((const uint2*)(xin + (size_t)i2 * H))[lane];
        uint2 d = ((const uint2*)(xin + (size_t)i3 * H))[lane];
        acc_h4(a, ax, ay, az, aw);
        acc_h4(b, ax, ay, az, aw);
        acc_h4(c, ax, ay, az, aw);
        acc_h4(d, ax, ay, az, aw);
    }
    for (; j < s1; j++) {
        int i0 = g_csrsrc[j];
        uint2 a = ((const uint2*)(xin + (size_t)i0 * H))[lane];
        acc_h4(a, ax, ay, az, aw);
    }
    float inv = g_invdeg[node];
    *(float4*)(s_tile + w * SROW + lane * 4) = make_float4(ax * inv, ay * inv, az * inv, aw * inv);
    __syncthreads();
    if (tid < 256) {
        int ks = tid >> 5, ln = tid & 31;
        int g = ln >> 2, tg = ln & 3;
        const float* rA = s_tile + g * SROW;
        const float* rB = s_tile + (g + 8) * SROW;
        int c = ks * 16 + tg * 2;
        uint4 ah, al;
        split2(rA[c], rA[c + 1], ah.x, al.x);
        split2(rB[c], rB[c + 1], ah.y, al.y);
        split2(rA[c + 8], rA[c + 9], ah.z, al.z);
        split2(rB[c + 8], rB[c + 9], ah.w, al.w);
        uint4* fd = (uint4*)(g_fragAgg + ((size_t)(tile * 8 + ks) * 32 + ln) * 32);
        fd[0] = ah; fd[1] = al;
    }
}

// ---------------- W fragment build ----------------
__global__ void k_conv_w(const float* __restrict__ Wl, const float* __restrict__ Wr,
                         const float* __restrict__ jkW) {
    int idx = blockIdx.x * blockDim.x + threadIdx.x;
    if (idx >= 5 * 16 * 16 * 32) return;
    int lane = idx & 31;
    int ks = (idx >> 5) & 15;
    int nt = (idx >> 9) & 15;
    int tgt = idx >> 13;
    int g = lane >> 2, tg = lane & 3;
    int n = nt * 8 + g;
    int k = ks * 16 + tg * 2;

    float v[4];
    if (tgt < 3) {
        #pragma unroll
        for (int q = 0; q < 4; q++) {
            int kk = k + (q >> 1) * 8 + (q & 1);
            v[q] = (kk < 128) ? Wl[(size_t)tgt * 16384 + n * 128 + kk]
                              : Wr[(size_t)tgt * 16384 + n * 128 + kk - 128];
        }
    } else {
        int h = tgt - 3;
        #pragma unroll
        for (int q = 0; q < 4; q++) {
            int kk = k + (q >> 1) * 8 + (q & 1);
            v[q] = jkW[(size_t)n * 512 + h * 256 + kk];
        }
    }
    uint32_t bh0, bl0, bh1, bl1;
    split2(v[0], v[1], bh0, bl0);
    split2(v[2], v[3], bh1, bl1);
    *(uint4*)(g_wfrag + (size_t)tgt * 131072 + ((size_t)((nt * 16 + ks) * 32 + lane)) * 16)
        = make_uint4(bh0, bh1, bl0, bl1);
}

// ---------------- mma helper ----------------
__device__ __forceinline__ void mma_bf16(float* c, uint4 a, uint32_t b0, uint32_t b1) {
    asm volatile(
        "mma.sync.aligned.m16n8k16.row.col.f32.bf16.bf16.f32 "
        "{%0,%1,%2,%3}, {%4,%5,%6,%7}, {%8,%9}, {%0,%1,%2,%3};"
        : "+f"(c[0]), "+f"(c[1]), "+f"(c[2]), "+f"(c[3])
        : "r"(a.x), "r"(a.y), "r"(a.z), "r"(a.w), "r"(b0), "r"(b1));
}

// ================= persistent layer GEMM (R8 + fp16 mirror write) =================
#define MMA_SMEM (131072 + 3 * 128 * 4)
__global__ void __launch_bounds__(256, 1) k_mma(
    int layer, const float* __restrict__ bias, const float* __restrict__ gamma,
    const float* __restrict__ beta)
{
    extern __shared__ uint8_t smem[];
    float* s_par = (float*)(smem + 131072);
    int tid = threadIdx.x, w = tid >> 5, lane = tid & 31;
    int g = lane >> 2, tg = lane & 3;

    if (tid < 128) {
        s_par[tid] = bias[tid];
        s_par[128 + tid] = gamma[tid];
        s_par[256 + tid] = beta[tid];
    }
    {
        const uint4* wsrc = (const uint4*)(g_wfrag + (size_t)layer * 131072);
        uint4* wdst = (uint4*)smem;
        #pragma unroll
        for (int i = 0; i < 32; i++) wdst[tid + i * 256] = wsrc[tid + i * 256];
    }
    __syncthreads();

    const uint8_t* fragXl = g_fragX[layer];
    const float* xin = g_X[layer];
    float* xout = g_X[layer + 1];
    __half* xhout = (layer < 2) ? g_Xh[layer + 1] : (__half*)nullptr;
    uint8_t* fragout = g_fragX[layer + 1];
    bool wr_float = (layer < 2);

    for (int tb = blockIdx.x; tb < NTILE; tb += gridDim.x) {
        int mt = tb * 8 + w;
        size_t m0 = (size_t)mt * 16 + g, m1 = m0 + 8;

        float acc[16][4];
        #pragma unroll
        for (int nt = 0; nt < 16; nt++)
            #pragma unroll
            for (int q = 0; q < 4; q++) acc[nt][q] = 0.f;

        for (int ksl = 0; ksl < 16; ksl++) {
            const uint8_t* asrc = (ksl < 8) ? g_fragAgg : fragXl;
            int kloc = ksl & 7;
            const uint4* ap = (const uint4*)(asrc + ((size_t)(mt * 8 + kloc) * 32 + lane) * 32);
            uint4 ah = ap[0], al = ap[1];
            #pragma unroll
            for (int nt = 0; nt < 16; nt++) {
                uint4 b = ((const uint4*)smem)[(nt * 16 + ksl) * 32 + lane];
                mma_bf16(acc[nt], ah, b.x, b.y);
                mma_bf16(acc[nt], ah, b.z, b.w);
                mma_bf16(acc[nt], al, b.x, b.y);
            }
        }

        #pragma unroll
        for (int nt = 0; nt < 16; nt++) {
            int n0 = nt * 8 + tg * 2;
            float b0 = s_par[n0], b1 = s_par[n0 + 1];
            acc[nt][0] += b0; acc[nt][1] += b1;
            acc[nt][2] += b0; acc[nt][3] += b1;
        }
        float s0 = 0.f, q0 = 0.f, s1 = 0.f, q1 = 0.f;
        #pragma unroll
        for (int nt = 0; nt < 16; nt++) {
            s0 += acc[nt][0] + acc[nt][1];
            q0 += acc[nt][0] * acc[nt][0] + acc[nt][1] * acc[nt][1];
            s1 += acc[nt][2] + acc[nt][3];
            q1 += acc[nt][2] * acc[nt][2] + acc[nt][3] * acc[nt][3];
        }
        #pragma unroll
        for (int o = 1; o <= 2; o <<= 1) {
            s0 += __shfl_xor_sync(0xffffffffu, s0, o);
            q0 += __shfl_xor_sync(0xffffffffu, q0, o);
            s1 += __shfl_xor_sync(0xffffffffu, s1, o);
            q1 += __shfl_xor_sync(0xffffffffu, q1, o);
        }
        float mu0 = s0 * (1.0f / H), mu1 = s1 * (1.0f / H);
        float rs0 = rsqrtf(q0 * (1.0f / H) - mu0 * mu0 + 1e-5f);
        float rs1 = rsqrtf(q1 * (1.0f / H) - mu1 * mu1 + 1e-5f);

        #pragma unroll
        for (int ks2 = 0; ks2 < 8; ks2++) {
            float2 oa0, oa1, ob0, ob1;
            #pragma unroll
            for (int half = 0; half < 2; half++) {
                int nt = 2 * ks2 + half;
                int n0 = nt * 8 + tg * 2;
                float ga0 = s_par[128 + n0], ga1 = s_par[128 + n0 + 1];
                float be0 = s_par[256 + n0], be1 = s_par[256 + n0 + 1];
                float2 o0, o1;
                o0.x = fmaxf((acc[nt][0] - mu0) * rs0 * ga0 + be0, 0.f);
                o0.y = fmaxf((acc[nt][1] - mu0) * rs0 * ga1 + be1, 0.f);
                o1.x = fmaxf((acc[nt][2] - mu1) * rs1 * ga0 + be0, 0.f);
                o1.y = fmaxf((acc[nt][3] - mu1) * rs1 * ga1 + be1, 0.f);
                if (layer > 0) {
                    float2 r0 = *(const float2*)(xin + m0 * H + n0);
                    float2 r1 = *(const float2*)(xin + m1 * H + n0);
                    o0.x += r0.x; o0.y += r0.y;
                    o1.x += r1.x; o1.y += r1.y;
                }
                if (wr_float) {
                    *(float2*)(xout + m0 * H + n0) = o0;
                    *(float2*)(xout + m1 * H + n0) = o1;
                    __half2 h0 = __floats2half2_rn(o0.x, o0.y);
                    __half2 h1 = __floats2half2_rn(o1.x, o1.y);
                    *(uint32_t*)(xhout + m0 * H + n0) = *(uint32_t*)&h0;
                    *(uint32_t*)(xhout + m1 * H + n0) = *(uint32_t*)&h1;
                }
                if (half == 0) { oa0 = o0; oa1 = o1; }
                else           { ob0 = o0; ob1 = o1; }
            }
            uint4 ah, al;
            split2(oa0.x, oa0.y, ah.x, al.x);
            split2(oa1.x, oa1.y, ah.y, al.y);
            split2(ob0.x, ob0.y, ah.z, al.z);
            split2(ob1.x, ob1.y, ah.w, al.w);
            uint4* fd = (uint4*)(fragout + ((size_t)(mt * 8 + ks2) * 32 + lane) * 32);
            fd[0] = ah; fd[1] = al;
        }
    }
}

// ================= JK (exact R8): 2 K=256 phases, W blob per phase =================
#define JK_SMEM (131072 + 512)
__global__ void __launch_bounds__(256, 1) k_jk(
    const float* __restrict__ jkb, float* __restrict__ outp)
{
    extern __shared__ uint8_t smem[];
    float* s_bias = (float*)(smem + 131072);
    int tid = threadIdx.x, w = tid >> 5, lane = tid & 31;
    int g = lane >> 2, tg = lane & 3;
    int mt = blockIdx.x * 8 + w;
    size_t m0 = (size_t)mt * 16 + g, m1 = m0 + 8;

    if (tid < 128) s_bias[tid] = jkb[tid];

    float acc[16][4];
    #pragma unroll
    for (int nt = 0; nt < 16; nt++)
        #pragma unroll
        for (int q = 0; q < 4; q++) acc[nt][q] = 0.f;

    for (int ph = 0; ph < 2; ph++) {
        __syncthreads();
        {
            const uint4* wsrc = (const uint4*)(g_wfrag + (size_t)(3 + ph) * 131072);
            uint4* wdst = (uint4*)smem;
            #pragma unroll
            for (int i = 0; i < 32; i++) wdst[tid + i * 256] = wsrc[tid + i * 256];
        }
        __syncthreads();
        for (int ksl = 0; ksl < 16; ksl++) {
            int gks = ph * 16 + ksl;
            const uint4* ap = (const uint4*)(g_fragX[gks >> 3]
                              + ((size_t)(mt * 8 + (gks & 7)) * 32 + lane) * 32);
            uint4 ah = ap[0], al = ap[1];
            #pragma unroll
            for (int nt = 0; nt < 16; nt++) {
                uint4 b = ((const uint4*)smem)[(nt * 16 + ksl) * 32 + lane];
                mma_bf16(acc[nt], ah, b.x, b.y);
                mma_bf16(acc[nt], ah, b.z, b.w);
                mma_bf16(acc[nt], al, b.x, b.y);
            }
        }
    }

    bool w0 = m0 < (size_t)NNODES, w1 = m1 < (size_t)NNODES;
    #pragma unroll
    for (int nt = 0; nt < 16; nt++) {
        int n0 = nt * 8 + tg * 2;
        float b0 = s_bias[n0], b1 = s_bias[n0 + 1];
        if (w0) *(float2*)(outp + m0 * H + n0) = make_float2(acc[nt][0] + b0, acc[nt][1] + b1);
        if (w1) *(float2*)(outp + m1 * H + n0) = make_float2(acc[nt][2] + b0, acc[nt][3] + b1);
    }
}

// ---------------- launch ----------------
extern "C" void kernel_launch(void* const* d_in, const int* in_sizes, int n_in,
                              void* d_out, int out_size) {
    const float* emb = (const float*)d_in[0];
    const float* Wl  = (const float*)d_in[1];
    const float* bl  = (const float*)d_in[2];
    const float* Wr  = (const float*)d_in[3];
    const float* lg  = (const float*)d_in[4];
    const float* lb  = (const float*)d_in[5];
    const float* jkW = (const float*)d_in[6];
    const float* jkb = (const float*)d_in[7];
    const int*   ei  = (const int*)d_in[8];
    int E = in_sizes[8] / 2;
    const int* src = ei;
    const int* dst = ei + E;
    float* out = (float*)d_out;

    cudaFuncSetAttribute(k_mma, cudaFuncAttributeMaxDynamicSharedMemorySize, MMA_SMEM);
    cudaFuncSetAttribute(k_jk,  cudaFuncAttributeMaxDynamicSharedMemorySize, JK_SMEM);

    k_zero_deg<<<(NP + 255) / 256, 256>>>();
    k_hist<<<(E + 255) / 256, 256>>>(dst, E);
    k_scan1<<<NBLK, 1024>>>();
    k_scan2<<<1, 128>>>();
    k_scan3<<<(NP + 255) / 256, 256>>>();
    k_fill<<<(E + 255) / 256, 256>>>(src, dst, E);
    k_emb_frag<<<NT16, 256>>>(emb);
    k_conv_w<<<(5 * 16 * 16 * 32 + 255) / 256, 256>>>(Wl, Wr, jkW);

    for (int l = 0; l < 3; l++) {
        k_agg<<<NT16, 512>>>(l);
        k_mma<<<148, 256, MMA_SMEM>>>(l, bl + l * H, lg + l * H, lb + l * H);
    }
    k_jk<<<NTILE, 256, JK_SMEM>>>(jkb, out);
}

// round 15
// speedup vs baseline: 1.1900x; 1.1066x over previous
#include <cuda_runtime.h>
#include <cuda_bf16.h>
#include <cuda_fp16.h>
#include <cstdint>

#define NNODES 100000
#define NP     100352            // multiple of 1024 and 128
#define H      128
#define EMAX   1600000
#define NT16   (NP / 16)
#define NTILE  (NP / 128)        // 784 GEMM tiles
#define NBLK   (NP / 1024)       // 98 scan blocks

// ---------------- device scratch ----------------
__device__ float  g_X[4][(size_t)NP * H];
__device__ __half g_Xh[3][(size_t)NP * H];     // fp16 mirror of X0..X2 (gather source)
__device__ int    g_deg[NP];
__device__ float  g_invdeg[NP];
__device__ int    g_rowstart[NP + 1];
__device__ int    g_cursor[NP];
__device__ int    g_csrsrc[EMAX];
__device__ int    g_blocksum[NBLK];
// W fragments: tgt t (0..4): addr = t*131072 + ((nt*16 + ks)*32 + lane)*16
__device__ uint8_t g_wfrag[5 * 131072];
// A fragments: [tile][ks 0..7][lane]*32B
__device__ uint8_t g_fragAgg[(size_t)NT16 * 8192];
__device__ uint8_t g_fragX[4][(size_t)NT16 * 8192];

// ---------------- bf16 hi/lo split ----------------
__device__ __forceinline__ void split2(float v0, float v1, uint32_t& ph, uint32_t& pl) {
    __nv_bfloat16 h0 = __float2bfloat16(v0), h1 = __float2bfloat16(v1);
    float r0 = v0 - __bfloat162float(h0), r1 = v1 - __bfloat162float(h1);
    __nv_bfloat16 l0 = __float2bfloat16(r0), l1 = __float2bfloat16(r1);
    ph = ((uint32_t)__bfloat16_as_ushort(h1) << 16) | (uint32_t)__bfloat16_as_ushort(h0);
    pl = ((uint32_t)__bfloat16_as_ushort(l1) << 16) | (uint32_t)__bfloat16_as_ushort(l0);
}

// ---------------- CSR build ----------------
__global__ void k_zero_deg() {
    int i = blockIdx.x * blockDim.x + threadIdx.x;
    if (i < NP) g_deg[i] = 0;
}
__global__ void k_hist(const int* __restrict__ dst, int E) {
    int i = blockIdx.x * blockDim.x + threadIdx.x;
    if (i < E) atomicAdd(&g_deg[dst[i]], 1);
}
__global__ void __launch_bounds__(1024) k_scan1() {
    __shared__ int wt[32];
    int t = threadIdx.x, lane = t & 31, wid = t >> 5;
    int i = blockIdx.x * 1024 + t;
    int v = g_deg[i];
    int x = v;
    #pragma unroll
    for (int d = 1; d < 32; d <<= 1) {
        int y = __shfl_up_sync(0xffffffffu, x, d);
        if (lane >= d) x += y;
    }
    if (lane == 31) wt[wid] = x;
    __syncthreads();
    if (wid == 0) {
        int y = wt[lane];
        #pragma unroll
        for (int d = 1; d < 32; d <<= 1) {
            int z = __shfl_up_sync(0xffffffffu, y, d);
            if (lane >= d) y += z;
        }
        wt[lane] = y;
    }
    __syncthreads();
    int off = (wid == 0) ? 0 : wt[wid - 1];
    g_rowstart[i] = off + x - v;
    if (t == 1023) g_blocksum[blockIdx.x] = off + x;
    g_invdeg[i] = 1.0f / fmaxf((float)v, 1.0f);
    g_cursor[i] = 0;
}
__global__ void k_scan2() {
    __shared__ int wt[4];
    int t = threadIdx.x, lane = t & 31, wid = t >> 5;
    int v = (t < NBLK) ? g_blocksum[t] : 0;
    int x = v;
    #pragma unroll
    for (int d = 1; d < 32; d <<= 1) {
        int y = __shfl_up_sync(0xffffffffu, x, d);
        if (lane >= d) x += y;
    }
    if (lane == 31) wt[wid] = x;
    __syncthreads();
    if (t == 0) {
        int r = 0;
        #pragma unroll
        for (int w = 0; w < 4; w++) { int tmp = wt[w]; wt[w] = r; r += tmp; }
        g_rowstart[NP] = r;
    }
    __syncthreads();
    if (t < NBLK) g_blocksum[t] = wt[wid] + x - v;
}
__global__ void k_scan3() {
    int i = blockIdx.x * blockDim.x + threadIdx.x;
    if (i < NP) g_rowstart[i] += g_blocksum[i >> 10];
}
__global__ void k_fill(const int* __restrict__ src, const int* __restrict__ dst, int E) {
    int i = blockIdx.x * blockDim.x + threadIdx.x;
    if (i < E) {
        int d = dst[i];
        int p = atomicAdd(&g_cursor[d], 1);
        g_csrsrc[g_rowstart[d] + p] = src[i];
    }
}

// ---------------- emb: float copy + fp16 mirror + frag conversion ----------------
#define SROW 132
__global__ void __launch_bounds__(256) k_emb_frag(const float* __restrict__ emb) {
    __shared__ float s_tile[16 * SROW];
    int tid = threadIdx.x;
    int tile = blockIdx.x;
    size_t rowBase = (size_t)tile * 16;
    #pragma unroll
    for (int i = 0; i < 2; i++) {
        int idx = tid + i * 256;
        int r = idx >> 5, c4 = idx & 31;
        size_t row = rowBase + r;
        float4 v = make_float4(0.f, 0.f, 0.f, 0.f);
        if (row < (size_t)NNODES) v = ((const float4*)(emb + row * H))[c4];
        *(float4*)(s_tile + r * SROW + c4 * 4) = v;
        ((float4*)(g_X[0] + row * H))[c4] = v;
        __half2 h01 = __floats2half2_rn(v.x, v.y);
        __half2 h23 = __floats2half2_rn(v.z, v.w);
        uint2 hp = make_uint2(*(uint32_t*)&h01, *(uint32_t*)&h23);
        ((uint2*)(g_Xh[0] + row * H))[c4] = hp;
    }
    __syncthreads();
    {
        int ks = tid >> 5, lane = tid & 31;
        int g = lane >> 2, tg = lane & 3;
        const float* rA = s_tile + g * SROW;
        const float* rB = s_tile + (g + 8) * SROW;
        int c = ks * 16 + tg * 2;
        uint4 ah, al;
        split2(rA[c], rA[c + 1], ah.x, al.x);
        split2(rB[c], rB[c + 1], ah.y, al.y);
        split2(rA[c + 8], rA[c + 9], ah.z, al.z);
        split2(rB[c + 8], rB[c + 9], ah.w, al.w);
        uint4* fd = (uint4*)(g_fragX[0] + ((size_t)(tile * 8 + ks) * 32 + lane) * 32);
        fd[0] = ah; fd[1] = al;
    }
}

// ---------------- aggregation: warp/node, fp16 gather MLP=8, tile->frag via smem ----------------
__device__ __forceinline__ void acc_h4(uint2 u, float& a0, float& a1, float& a2, float& a3) {
    float2 f01 = __half22float2(*(__half2*)&u.x);
    float2 f23 = __half22float2(*(__half2*)&u.y);
    a0 += f01.x; a1 += f01.y; a2 += f23.x; a3 += f23.y;
}
__global__ void __launch_bounds__(512) k_agg(int layer) {
    __shared__ float s_tile[16 * SROW];
    int tid = threadIdx.x, w = tid >> 5, lane = tid & 31;
    int tile = blockIdx.x;
    int node = tile * 16 + w;
    const __half* __restrict__ xin = g_Xh[layer];
    int s0 = g_rowstart[node], s1 = g_rowstart[node + 1];
    float ax = 0.f, ay = 0.f, az = 0.f, aw = 0.f;
    int j = s0;
    for (; j + 8 <= s1; j += 8) {
        int ix[8];
        #pragma unroll
        for (int q = 0; q < 8; q++) ix[q] = g_csrsrc[j + q];
        uint2 v[8];
        #pragma unroll
        for (int q = 0; q < 8; q++)
            v[q] = ((const uint2*)(xin + (size_t)ix[q] * H))[lane];
        #pragma unroll
        for (int q = 0; q < 8; q++) acc_h4(v[q], ax, ay, az, aw);
    }
    for (; j < s1; j++) {
        int i0 = g_csrsrc[j];
        uint2 a = ((const uint2*)(xin + (size_t)i0 * H))[lane];
        acc_h4(a, ax, ay, az, aw);
    }
    float inv = g_invdeg[node];
    *(float4*)(s_tile + w * SROW + lane * 4) = make_float4(ax * inv, ay * inv, az * inv, aw * inv);
    __syncthreads();
    if (tid < 256) {
        int ks = tid >> 5, ln = tid & 31;
        int g = ln >> 2, tg = ln & 3;
        const float* rA = s_tile + g * SROW;
        const float* rB = s_tile + (g + 8) * SROW;
        int c = ks * 16 + tg * 2;
        uint4 ah, al;
        split2(rA[c], rA[c + 1], ah.x, al.x);
        split2(rB[c], rB[c + 1], ah.y, al.y);
        split2(rA[c + 8], rA[c + 9], ah.z, al.z);
        split2(rB[c + 8], rB[c + 9], ah.w, al.w);
        uint4* fd = (uint4*)(g_fragAgg + ((size_t)(tile * 8 + ks) * 32 + ln) * 32);
        fd[0] = ah; fd[1] = al;
    }
}

// ---------------- W fragment build ----------------
__global__ void k_conv_w(const float* __restrict__ Wl, const float* __restrict__ Wr,
                         const float* __restrict__ jkW) {
    int idx = blockIdx.x * blockDim.x + threadIdx.x;
    if (idx >= 5 * 16 * 16 * 32) return;
    int lane = idx & 31;
    int ks = (idx >> 5) & 15;
    int nt = (idx >> 9) & 15;
    int tgt = idx >> 13;
    int g = lane >> 2, tg = lane & 3;
    int n = nt * 8 + g;
    int k = ks * 16 + tg * 2;

    float v[4];
    if (tgt < 3) {
        #pragma unroll
        for (int q = 0; q < 4; q++) {
            int kk = k + (q >> 1) * 8 + (q & 1);
            v[q] = (kk < 128) ? Wl[(size_t)tgt * 16384 + n * 128 + kk]
                              : Wr[(size_t)tgt * 16384 + n * 128 + kk - 128];
        }
    } else {
        int h = tgt - 3;
        #pragma unroll
        for (int q = 0; q < 4; q++) {
            int kk = k + (q >> 1) * 8 + (q & 1);
            v[q] = jkW[(size_t)n * 512 + h * 256 + kk];
        }
    }
    uint32_t bh0, bl0, bh1, bl1;
    split2(v[0], v[1], bh0, bl0);
    split2(v[2], v[3], bh1, bl1);
    *(uint4*)(g_wfrag + (size_t)tgt * 131072 + ((size_t)((nt * 16 + ks) * 32 + lane)) * 16)
        = make_uint4(bh0, bh1, bl0, bl1);
}

// ---------------- mma helper ----------------
__device__ __forceinline__ void mma_bf16(float* c, uint4 a, uint32_t b0, uint32_t b1) {
    asm volatile(
        "mma.sync.aligned.m16n8k16.row.col.f32.bf16.bf16.f32 "
        "{%0,%1,%2,%3}, {%4,%5,%6,%7}, {%8,%9}, {%0,%1,%2,%3};"
        : "+f"(c[0]), "+f"(c[1]), "+f"(c[2]), "+f"(c[3])
        : "r"(a.x), "r"(a.y), "r"(a.z), "r"(a.w), "r"(b0), "r"(b1));
}

// ================= persistent layer GEMM (R12 + A-frag prefetch pipeline) =================
#define MMA_SMEM (131072 + 3 * 128 * 4)
__global__ void __launch_bounds__(256, 1) k_mma(
    int layer, const float* __restrict__ bias, const float* __restrict__ gamma,
    const float* __restrict__ beta)
{
    extern __shared__ uint8_t smem[];
    float* s_par = (float*)(smem + 131072);
    int tid = threadIdx.x, w = tid >> 5, lane = tid & 31;
    int g = lane >> 2, tg = lane & 3;

    if (tid < 128) {
        s_par[tid] = bias[tid];
        s_par[128 + tid] = gamma[tid];
        s_par[256 + tid] = beta[tid];
    }
    {
        const uint4* wsrc = (const uint4*)(g_wfrag + (size_t)layer * 131072);
        uint4* wdst = (uint4*)smem;
        #pragma unroll
        for (int i = 0; i < 32; i++) wdst[tid + i * 256] = wsrc[tid + i * 256];
    }
    __syncthreads();

    const uint8_t* fragXl = g_fragX[layer];
    const float* xin = g_X[layer];
    float* xout = g_X[layer + 1];
    __half* xhout = (layer < 2) ? g_Xh[layer + 1] : (__half*)nullptr;
    uint8_t* fragout = g_fragX[layer + 1];
    bool wr_float = (layer < 2);

    for (int tb = blockIdx.x; tb < NTILE; tb += gridDim.x) {
        int mt = tb * 8 + w;
        size_t m0 = (size_t)mt * 16 + g, m1 = m0 + 8;

        float acc[16][4];
        #pragma unroll
        for (int nt = 0; nt < 16; nt++)
            #pragma unroll
            for (int q = 0; q < 4; q++) acc[nt][q] = 0.f;

        // prefetch ksl=0
        const uint4* ap0 = (const uint4*)(g_fragAgg + ((size_t)(mt * 8) * 32 + lane) * 32);
        uint4 ah = ap0[0], al = ap0[1];
        for (int ksl = 0; ksl < 16; ksl++) {
            uint4 nah, nal;
            if (ksl < 15) {
                int nk = ksl + 1;
                const uint8_t* asrc = (nk < 8) ? g_fragAgg : fragXl;
                const uint4* ap = (const uint4*)(asrc + ((size_t)(mt * 8 + (nk & 7)) * 32 + lane) * 32);
                nah = ap[0]; nal = ap[1];
            }
            #pragma unroll
            for (int nt = 0; nt < 16; nt++) {
                uint4 b = ((const uint4*)smem)[(nt * 16 + ksl) * 32 + lane];
                mma_bf16(acc[nt], ah, b.x, b.y);
                mma_bf16(acc[nt], ah, b.z, b.w);
                mma_bf16(acc[nt], al, b.x, b.y);
            }
            if (ksl < 15) { ah = nah; al = nal; }
        }

        #pragma unroll
        for (int nt = 0; nt < 16; nt++) {
            int n0 = nt * 8 + tg * 2;
            float b0 = s_par[n0], b1 = s_par[n0 + 1];
            acc[nt][0] += b0; acc[nt][1] += b1;
            acc[nt][2] += b0; acc[nt][3] += b1;
        }
        float s0 = 0.f, q0 = 0.f, s1 = 0.f, q1 = 0.f;
        #pragma unroll
        for (int nt = 0; nt < 16; nt++) {
            s0 += acc[nt][0] + acc[nt][1];
            q0 += acc[nt][0] * acc[nt][0] + acc[nt][1] * acc[nt][1];
            s1 += acc[nt][2] + acc[nt][3];
            q1 += acc[nt][2] * acc[nt][2] + acc[nt][3] * acc[nt][3];
        }
        #pragma unroll
        for (int o = 1; o <= 2; o <<= 1) {
            s0 += __shfl_xor_sync(0xffffffffu, s0, o);
            q0 += __shfl_xor_sync(0xffffffffu, q0, o);
            s1 += __shfl_xor_sync(0xffffffffu, s1, o);
            q1 += __shfl_xor_sync(0xffffffffu, q1, o);
        }
        float mu0 = s0 * (1.0f / H), mu1 = s1 * (1.0f / H);
        float rs0 = rsqrtf(q0 * (1.0f / H) - mu0 * mu0 + 1e-5f);
        float rs1 = rsqrtf(q1 * (1.0f / H) - mu1 * mu1 + 1e-5f);

        #pragma unroll
        for (int ks2 = 0; ks2 < 8; ks2++) {
            float2 oa0, oa1, ob0, ob1;
            #pragma unroll
            for (int half = 0; half < 2; half++) {
                int nt = 2 * ks2 + half;
                int n0 = nt * 8 + tg * 2;
                float ga0 = s_par[128 + n0], ga1 = s_par[128 + n0 + 1];
                float be0 = s_par[256 + n0], be1 = s_par[256 + n0 + 1];
                float2 o0, o1;
                o0.x = fmaxf((acc[nt][0] - mu0) * rs0 * ga0 + be0, 0.f);
                o0.y = fmaxf((acc[nt][1] - mu0) * rs0 * ga1 + be1, 0.f);
                o1.x = fmaxf((acc[nt][2] - mu1) * rs1 * ga0 + be0, 0.f);
                o1.y = fmaxf((acc[nt][3] - mu1) * rs1 * ga1 + be1, 0.f);
                if (layer > 0) {
                    float2 r0 = *(const float2*)(xin + m0 * H + n0);
                    float2 r1 = *(const float2*)(xin + m1 * H + n0);
                    o0.x += r0.x; o0.y += r0.y;
                    o1.x += r1.x; o1.y += r1.y;
                }
                if (wr_float) {
                    *(float2*)(xout + m0 * H + n0) = o0;
                    *(float2*)(xout + m1 * H + n0) = o1;
                    __half2 h0 = __floats2half2_rn(o0.x, o0.y);
                    __half2 h1 = __floats2half2_rn(o1.x, o1.y);
                    *(uint32_t*)(xhout + m0 * H + n0) = *(uint32_t*)&h0;
                    *(uint32_t*)(xhout + m1 * H + n0) = *(uint32_t*)&h1;
                }
                if (half == 0) { oa0 = o0; oa1 = o1; }
                else           { ob0 = o0; ob1 = o1; }
            }
            uint4 fah, fal;
            split2(oa0.x, oa0.y, fah.x, fal.x);
            split2(oa1.x, oa1.y, fah.y, fal.y);
            split2(ob0.x, ob0.y, fah.z, fal.z);
            split2(ob1.x, ob1.y, fah.w, fal.w);
            uint4* fd = (uint4*)(fragout + ((size_t)(mt * 8 + ks2) * 32 + lane) * 32);
            fd[0] = fah; fd[1] = fal;
        }
    }
}

// ================= JK (R8 structure + A prefetch): 2 K=256 phases, W blob per phase ===========
#define JK_SMEM (131072 + 512)
__global__ void __launch_bounds__(256, 1) k_jk(
    const float* __restrict__ jkb, float* __restrict__ outp)
{
    extern __shared__ uint8_t smem[];
    float* s_bias = (float*)(smem + 131072);
    int tid = threadIdx.x, w = tid >> 5, lane = tid & 31;
    int g = lane >> 2, tg = lane & 3;
    int mt = blockIdx.x * 8 + w;
    size_t m0 = (size_t)mt * 16 + g, m1 = m0 + 8;

    if (tid < 128) s_bias[tid] = jkb[tid];

    float acc[16][4];
    #pragma unroll
    for (int nt = 0; nt < 16; nt++)
        #pragma unroll
        for (int q = 0; q < 4; q++) acc[nt][q] = 0.f;

    for (int ph = 0; ph < 2; ph++) {
        __syncthreads();
        {
            const uint4* wsrc = (const uint4*)(g_wfrag + (size_t)(3 + ph) * 131072);
            uint4* wdst = (uint4*)smem;
            #pragma unroll
            for (int i = 0; i < 32; i++) wdst[tid + i * 256] = wsrc[tid + i * 256];
        }
        __syncthreads();
        const uint4* ap0 = (const uint4*)(g_fragX[2 * ph]
                           + ((size_t)(mt * 8) * 32 + lane) * 32);
        uint4 ah = ap0[0], al = ap0[1];
        for (int ksl = 0; ksl < 16; ksl++) {
            uint4 nah, nal;
            if (ksl < 15) {
                int gk = ph * 16 + ksl + 1;
                const uint4* ap = (const uint4*)(g_fragX[gk >> 3]
                                  + ((size_t)(mt * 8 + (gk & 7)) * 32 + lane) * 32);
                nah = ap[0]; nal = ap[1];
            }
            #pragma unroll
            for (int nt = 0; nt < 16; nt++) {
                uint4 b = ((const uint4*)smem)[(nt * 16 + ksl) * 32 + lane];
                mma_bf16(acc[nt], ah, b.x, b.y);
                mma_bf16(acc[nt], ah, b.z, b.w);
                mma_bf16(acc[nt], al, b.x, b.y);
            }
            if (ksl < 15) { ah = nah; al = nal; }
        }
    }

    bool w0 = m0 < (size_t)NNODES, w1 = m1 < (size_t)NNODES;
    #pragma unroll
    for (int nt = 0; nt < 16; nt++) {
        int n0 = nt * 8 + tg * 2;
        float b0 = s_bias[n0], b1 = s_bias[n0 + 1];
        if (w0) *(float2*)(outp + m0 * H + n0) = make_float2(acc[nt][0] + b0, acc[nt][1] + b1);
        if (w1) *(float2*)(outp + m1 * H + n0) = make_float2(acc[nt][2] + b0, acc[nt][3] + b1);
    }
}

// ---------------- launch ----------------
extern "C" void kernel_launch(void* const* d_in, const int* in_sizes, int n_in,
                              void* d_out, int out_size) {
    const float* emb = (const float*)d_in[0];
    const float* Wl  = (const float*)d_in[1];
    const float* bl  = (const float*)d_in[2];
    const float* Wr  = (const float*)d_in[3];
    const float* lg  = (const float*)d_in[4];
    const float* lb  = (const float*)d_in[5];
    const float* jkW = (const float*)d_in[6];
    const float* jkb = (const float*)d_in[7];
    const int*   ei  = (const int*)d_in[8];
    int E = in_sizes[8] / 2;
    const int* src = ei;
    const int* dst = ei + E;
    float* out = (float*)d_out;

    cudaFuncSetAttribute(k_mma, cudaFuncAttributeMaxDynamicSharedMemorySize, MMA_SMEM);
    cudaFuncSetAttribute(k_jk,  cudaFuncAttributeMaxDynamicSharedMemorySize, JK_SMEM);

    k_zero_deg<<<(NP + 255) / 256, 256>>>();
    k_hist<<<(E + 255) / 256, 256>>>(dst, E);
    k_scan1<<<NBLK, 1024>>>();
    k_scan2<<<1, 128>>>();
    k_scan3<<<(NP + 255) / 256, 256>>>();
    k_fill<<<(E + 255) / 256, 256>>>(src, dst, E);
    k_emb_frag<<<NT16, 256>>>(emb);
    k_conv_w<<<(5 * 16 * 16 * 32 + 255) / 256, 256>>>(Wl, Wr, jkW);

    for (int l = 0; l < 3; l++) {
        k_agg<<<NT16, 512>>>(l);
        k_mma<<<148, 256, MMA_SMEM>>>(l, bl + l * H, lg + l * H, lb + l * H);
    }
    k_jk<<<NTILE, 256, JK_SMEM>>>(jkb, out);
}

// round 16
// speedup vs baseline: 1.3613x; 1.1439x over previous
#include <cuda_runtime.h>
#include <cuda_fp16.h>
#include <cstdint>

#define NNODES 100000
#define NP     100352            // multiple of 1024 and 128
#define H      128
#define EMAX   1600000
#define NT16   (NP / 16)
#define NTILE  (NP / 128)        // 784 GEMM tiles
#define NBLK   (NP / 1024)       // 98 scan blocks

// ---------------- device scratch ----------------
__device__ float  g_X[4][(size_t)NP * H];
__device__ __half g_Xh[3][(size_t)NP * H];     // fp16 mirror of X0..X2 (gather source)
__device__ int    g_deg[NP];
__device__ float  g_invdeg[NP];
__device__ int    g_rowstart[NP + 1];
__device__ int    g_cursor[NP];
__device__ int    g_csrsrc[EMAX];
__device__ int    g_blocksum[NBLK];
// W fragments (fp16 hi/lo): tgt t (0..4): addr = t*131072 + ((nt*16 + ks)*32 + lane)*16
//   uint4 = {wh0, wh1, wl0, wl1} as half2 each
__device__ uint8_t g_wfrag[5 * 131072];
// A fragments (fp16 single): [tile][ks 0..7][lane]*16B  ({a0,a1,a2,a3} as half2)
__device__ uint8_t g_fragAgg[(size_t)NT16 * 4096];
__device__ uint8_t g_fragX[4][(size_t)NT16 * 4096];

// ---------------- fp16 helpers ----------------
__device__ __forceinline__ uint32_t pack_h2(float v0, float v1) {
    __half2 h = __floats2half2_rn(v0, v1);
    return *(uint32_t*)&h;
}
// fp16 hi/lo split of a float pair
__device__ __forceinline__ void hsplit2(float v0, float v1, uint32_t& ph, uint32_t& pl) {
    __half h0 = __float2half_rn(v0), h1 = __float2half_rn(v1);
    float r0 = v0 - __half2float(h0), r1 = v1 - __half2float(h1);
    __half l0 = __float2half_rn(r0), l1 = __float2half_rn(r1);
    ph = ((uint32_t)__half_as_ushort(h1) << 16) | (uint32_t)__half_as_ushort(h0);
    pl = ((uint32_t)__half_as_ushort(l1) << 16) | (uint32_t)__half_as_ushort(l0);
}

// ---------------- CSR build ----------------
__global__ void k_zero_deg() {
    int i = blockIdx.x * blockDim.x + threadIdx.x;
    if (i < NP) g_deg[i] = 0;
}
__global__ void k_hist(const int* __restrict__ dst, int E) {
    int i = blockIdx.x * blockDim.x + threadIdx.x;
    if (i < E) atomicAdd(&g_deg[dst[i]], 1);
}
__global__ void __launch_bounds__(1024) k_scan1() {
    __shared__ int wt[32];
    int t = threadIdx.x, lane = t & 31, wid = t >> 5;
    int i = blockIdx.x * 1024 + t;
    int v = g_deg[i];
    int x = v;
    #pragma unroll
    for (int d = 1; d < 32; d <<= 1) {
        int y = __shfl_up_sync(0xffffffffu, x, d);
        if (lane >= d) x += y;
    }
    if (lane == 31) wt[wid] = x;
    __syncthreads();
    if (wid == 0) {
        int y = wt[lane];
        #pragma unroll
        for (int d = 1; d < 32; d <<= 1) {
            int z = __shfl_up_sync(0xffffffffu, y, d);
            if (lane >= d) y += z;
        }
        wt[lane] = y;
    }
    __syncthreads();
    int off = (wid == 0) ? 0 : wt[wid - 1];
    g_rowstart[i] = off + x - v;
    if (t == 1023) g_blocksum[blockIdx.x] = off + x;
    g_invdeg[i] = 1.0f / fmaxf((float)v, 1.0f);
    g_cursor[i] = 0;
}
__global__ void k_scan2() {
    __shared__ int wt[4];
    int t = threadIdx.x, lane = t & 31, wid = t >> 5;
    int v = (t < NBLK) ? g_blocksum[t] : 0;
    int x = v;
    #pragma unroll
    for (int d = 1; d < 32; d <<= 1) {
        int y = __shfl_up_sync(0xffffffffu, x, d);
        if (lane >= d) x += y;
    }
    if (lane == 31) wt[wid] = x;
    __syncthreads();
    if (t == 0) {
        int r = 0;
        #pragma unroll
        for (int w = 0; w < 4; w++) { int tmp = wt[w]; wt[w] = r; r += tmp; }
        g_rowstart[NP] = r;
    }
    __syncthreads();
    if (t < NBLK) g_blocksum[t] = wt[wid] + x - v;
}
__global__ void k_scan3() {
    int i = blockIdx.x * blockDim.x + threadIdx.x;
    if (i < NP) g_rowstart[i] += g_blocksum[i >> 10];
}
__global__ void k_fill(const int* __restrict__ src, const int* __restrict__ dst, int E) {
    int i = blockIdx.x * blockDim.x + threadIdx.x;
    if (i < E) {
        int d = dst[i];
        int p = atomicAdd(&g_cursor[d], 1);
        g_csrsrc[g_rowstart[d] + p] = src[i];
    }
}

// ---------------- frag emit from smem tile (fp16 single) ----------------
#define SROW 132
__device__ __forceinline__ void tile_to_frag_h(const float* s_tile, uint8_t* fragdst,
                                               int tile, int cid) {
    int ks = cid >> 5, lane = cid & 31;
    int g = lane >> 2, tg = lane & 3;
    const float* rA = s_tile + g * SROW;
    const float* rB = s_tile + (g + 8) * SROW;
    int c = ks * 16 + tg * 2;
    uint4 a;
    a.x = pack_h2(rA[c], rA[c + 1]);
    a.y = pack_h2(rB[c], rB[c + 1]);
    a.z = pack_h2(rA[c + 8], rA[c + 9]);
    a.w = pack_h2(rB[c + 8], rB[c + 9]);
    *(uint4*)(fragdst + ((size_t)(tile * 8 + ks) * 32 + lane) * 16) = a;
}

// ---------------- emb: float copy + fp16 mirror + frag conversion ----------------
__global__ void __launch_bounds__(256) k_emb_frag(const float* __restrict__ emb) {
    __shared__ float s_tile[16 * SROW];
    int tid = threadIdx.x;
    int tile = blockIdx.x;
    size_t rowBase = (size_t)tile * 16;
    #pragma unroll
    for (int i = 0; i < 2; i++) {
        int idx = tid + i * 256;
        int r = idx >> 5, c4 = idx & 31;
        size_t row = rowBase + r;
        float4 v = make_float4(0.f, 0.f, 0.f, 0.f);
        if (row < (size_t)NNODES) v = ((const float4*)(emb + row * H))[c4];
        *(float4*)(s_tile + r * SROW + c4 * 4) = v;
        ((float4*)(g_X[0] + row * H))[c4] = v;
        uint2 hp = make_uint2(pack_h2(v.x, v.y), pack_h2(v.z, v.w));
        ((uint2*)(g_Xh[0] + row * H))[c4] = hp;
    }
    __syncthreads();
    tile_to_frag_h(s_tile, g_fragX[0], tile, tid);
}

// ---------------- aggregation: warp/node, fp16 gather MLP=8, tile->frag ----------------
__device__ __forceinline__ void acc_h4(uint2 u, float& a0, float& a1, float& a2, float& a3) {
    float2 f01 = __half22float2(*(__half2*)&u.x);
    float2 f23 = __half22float2(*(__half2*)&u.y);
    a0 += f01.x; a1 += f01.y; a2 += f23.x; a3 += f23.y;
}
__global__ void __launch_bounds__(512) k_agg(int layer) {
    __shared__ float s_tile[16 * SROW];
    int tid = threadIdx.x, w = tid >> 5, lane = tid & 31;
    int tile = blockIdx.x;
    int node = tile * 16 + w;
    const __half* __restrict__ xin = g_Xh[layer];
    int s0 = g_rowstart[node], s1 = g_rowstart[node + 1];
    float ax = 0.f, ay = 0.f, az = 0.f, aw = 0.f;
    int j = s0;
    for (; j + 8 <= s1; j += 8) {
        int ix[8];
        #pragma unroll
        for (int q = 0; q < 8; q++) ix[q] = g_csrsrc[j + q];
        uint2 v[8];
        #pragma unroll
        for (int q = 0; q < 8; q++)
            v[q] = ((const uint2*)(xin + (size_t)ix[q] * H))[lane];
        #pragma unroll
        for (int q = 0; q < 8; q++) acc_h4(v[q], ax, ay, az, aw);
    }
    for (; j < s1; j++) {
        int i0 = g_csrsrc[j];
        uint2 a = ((const uint2*)(xin + (size_t)i0 * H))[lane];
        acc_h4(a, ax, ay, az, aw);
    }
    float inv = g_invdeg[node];
    *(float4*)(s_tile + w * SROW + lane * 4) = make_float4(ax * inv, ay * inv, az * inv, aw * inv);
    __syncthreads();
    if (tid < 256) tile_to_frag_h(s_tile, g_fragAgg, tile, tid);
}

// ---------------- W fragment build (fp16 hi/lo) ----------------
__global__ void k_conv_w(const float* __restrict__ Wl, const float* __restrict__ Wr,
                         const float* __restrict__ jkW) {
    int idx = blockIdx.x * blockDim.x + threadIdx.x;
    if (idx >= 5 * 16 * 16 * 32) return;
    int lane = idx & 31;
    int ks = (idx >> 5) & 15;
    int nt = (idx >> 9) & 15;
    int tgt = idx >> 13;
    int g = lane >> 2, tg = lane & 3;
    int n = nt * 8 + g;
    int k = ks * 16 + tg * 2;

    float v[4];
    if (tgt < 3) {
        #pragma unroll
        for (int q = 0; q < 4; q++) {
            int kk = k + (q >> 1) * 8 + (q & 1);
            v[q] = (kk < 128) ? Wl[(size_t)tgt * 16384 + n * 128 + kk]
                              : Wr[(size_t)tgt * 16384 + n * 128 + kk - 128];
        }
    } else {
        int h = tgt - 3;
        #pragma unroll
        for (int q = 0; q < 4; q++) {
            int kk = k + (q >> 1) * 8 + (q & 1);
            v[q] = jkW[(size_t)n * 512 + h * 256 + kk];
        }
    }
    uint32_t wh0, wl0, wh1, wl1;
    hsplit2(v[0], v[1], wh0, wl0);
    hsplit2(v[2], v[3], wh1, wl1);
    *(uint4*)(g_wfrag + (size_t)tgt * 131072 + ((size_t)((nt * 16 + ks) * 32 + lane)) * 16)
        = make_uint4(wh0, wh1, wl0, wl1);
}

// ---------------- mma helper (f16 kind) ----------------
__device__ __forceinline__ void mma_f16(float* c, uint4 a, uint32_t b0, uint32_t b1) {
    asm volatile(
        "mma.sync.aligned.m16n8k16.row.col.f32.f16.f16.f32 "
        "{%0,%1,%2,%3}, {%4,%5,%6,%7}, {%8,%9}, {%0,%1,%2,%3};"
        : "+f"(c[0]), "+f"(c[1]), "+f"(c[2]), "+f"(c[3])
        : "r"(a.x), "r"(a.y), "r"(a.z), "r"(a.w), "r"(b0), "r"(b1));
}

// ================= persistent layer GEMM (f16, 2 MMAs/chunk, A prefetch) =================
#define MMA_SMEM (131072 + 3 * 128 * 4)
__global__ void __launch_bounds__(256, 1) k_mma(
    int layer, const float* __restrict__ bias, const float* __restrict__ gamma,
    const float* __restrict__ beta)
{
    extern __shared__ uint8_t smem[];
    float* s_par = (float*)(smem + 131072);
    int tid = threadIdx.x, w = tid >> 5, lane = tid & 31;
    int g = lane >> 2, tg = lane & 3;

    if (tid < 128) {
        s_par[tid] = bias[tid];
        s_par[128 + tid] = gamma[tid];
        s_par[256 + tid] = beta[tid];
    }
    {
        const uint4* wsrc = (const uint4*)(g_wfrag + (size_t)layer * 131072);
        uint4* wdst = (uint4*)smem;
        #pragma unroll
        for (int i = 0; i < 32; i++) wdst[tid + i * 256] = wsrc[tid + i * 256];
    }
    __syncthreads();

    const uint8_t* fragXl = g_fragX[layer];
    const float* xin = g_X[layer];
    float* xout = g_X[layer + 1];
    __half* xhout = (layer < 2) ? g_Xh[layer + 1] : (__half*)nullptr;
    uint8_t* fragout = g_fragX[layer + 1];
    bool wr_float = (layer < 2);

    for (int tb = blockIdx.x; tb < NTILE; tb += gridDim.x) {
        int mt = tb * 8 + w;
        size_t m0 = (size_t)mt * 16 + g, m1 = m0 + 8;

        float acc[16][4];
        #pragma unroll
        for (int nt = 0; nt < 16; nt++)
            #pragma unroll
            for (int q = 0; q < 4; q++) acc[nt][q] = 0.f;

        // prefetch ksl=0
        uint4 ah = *(const uint4*)(g_fragAgg + ((size_t)(mt * 8) * 32 + lane) * 16);
        for (int ksl = 0; ksl < 16; ksl++) {
            uint4 nah;
            if (ksl < 15) {
                int nk = ksl + 1;
                const uint8_t* asrc = (nk < 8) ? g_fragAgg : fragXl;
                nah = *(const uint4*)(asrc + ((size_t)(mt * 8 + (nk & 7)) * 32 + lane) * 16);
            }
            #pragma unroll
            for (int nt = 0; nt < 16; nt++) {
                uint4 b = ((const uint4*)smem)[(nt * 16 + ksl) * 32 + lane];
                mma_f16(acc[nt], ah, b.x, b.y);   // a * wh
                mma_f16(acc[nt], ah, b.z, b.w);   // a * wl
            }
            if (ksl < 15) ah = nah;
        }

        #pragma unroll
        for (int nt = 0; nt < 16; nt++) {
            int n0 = nt * 8 + tg * 2;
            float b0 = s_par[n0], b1 = s_par[n0 + 1];
            acc[nt][0] += b0; acc[nt][1] += b1;
            acc[nt][2] += b0; acc[nt][3] += b1;
        }
        float s0 = 0.f, q0 = 0.f, s1 = 0.f, q1 = 0.f;
        #pragma unroll
        for (int nt = 0; nt < 16; nt++) {
            s0 += acc[nt][0] + acc[nt][1];
            q0 += acc[nt][0] * acc[nt][0] + acc[nt][1] * acc[nt][1];
            s1 += acc[nt][2] + acc[nt][3];
            q1 += acc[nt][2] * acc[nt][2] + acc[nt][3] * acc[nt][3];
        }
        #pragma unroll
        for (int o = 1; o <= 2; o <<= 1) {
            s0 += __shfl_xor_sync(0xffffffffu, s0, o);
            q0 += __shfl_xor_sync(0xffffffffu, q0, o);
            s1 += __shfl_xor_sync(0xffffffffu, s1, o);
            q1 += __shfl_xor_sync(0xffffffffu, q1, o);
        }
        float mu0 = s0 * (1.0f / H), mu1 = s1 * (1.0f / H);
        float rs0 = rsqrtf(q0 * (1.0f / H) - mu0 * mu0 + 1e-5f);
        float rs1 = rsqrtf(q1 * (1.0f / H) - mu1 * mu1 + 1e-5f);

        #pragma unroll
        for (int ks2 = 0; ks2 < 8; ks2++) {
            float2 oa0, oa1, ob0, ob1;
            #pragma unroll
            for (int half = 0; half < 2; half++) {
                int nt = 2 * ks2 + half;
                int n0 = nt * 8 + tg * 2;
                float ga0 = s_par[128 + n0], ga1 = s_par[128 + n0 + 1];
                float be0 = s_par[256 + n0], be1 = s_par[256 + n0 + 1];
                float2 o0, o1;
                o0.x = fmaxf((acc[nt][0] - mu0) * rs0 * ga0 + be0, 0.f);
                o0.y = fmaxf((acc[nt][1] - mu0) * rs0 * ga1 + be1, 0.f);
                o1.x = fmaxf((acc[nt][2] - mu1) * rs1 * ga0 + be0, 0.f);
                o1.y = fmaxf((acc[nt][3] - mu1) * rs1 * ga1 + be1, 0.f);
                if (layer > 0) {
                    float2 r0 = *(const float2*)(xin + m0 * H + n0);
                    float2 r1 = *(const float2*)(xin + m1 * H + n0);
                    o0.x += r0.x; o0.y += r0.y;
                    o1.x += r1.x; o1.y += r1.y;
                }
                if (wr_float) {
                    *(float2*)(xout + m0 * H + n0) = o0;
                    *(float2*)(xout + m1 * H + n0) = o1;
                    *(uint32_t*)(xhout + m0 * H + n0) = pack_h2(o0.x, o0.y);
                    *(uint32_t*)(xhout + m1 * H + n0) = pack_h2(o1.x, o1.y);
                }
                if (half == 0) { oa0 = o0; oa1 = o1; }
                else           { ob0 = o0; ob1 = o1; }
            }
            uint4 fa;
            fa.x = pack_h2(oa0.x, oa0.y);
            fa.y = pack_h2(oa1.x, oa1.y);
            fa.z = pack_h2(ob0.x, ob0.y);
            fa.w = pack_h2(ob1.x, ob1.y);
            *(uint4*)(fragout + ((size_t)(mt * 8 + ks2) * 32 + lane) * 16) = fa;
        }
    }
}

// ================= JK (f16, 2 MMAs/chunk, A prefetch): 2 K=256 phases =================
#define JK_SMEM (131072 + 512)
__global__ void __launch_bounds__(256, 1) k_jk(
    const float* __restrict__ jkb, float* __restrict__ outp)
{
    extern __shared__ uint8_t smem[];
    float* s_bias = (float*)(smem + 131072);
    int tid = threadIdx.x, w = tid >> 5, lane = tid & 31;
    int g = lane >> 2, tg = lane & 3;
    int mt = blockIdx.x * 8 + w;
    size_t m0 = (size_t)mt * 16 + g, m1 = m0 + 8;

    if (tid < 128) s_bias[tid] = jkb[tid];

    float acc[16][4];
    #pragma unroll
    for (int nt = 0; nt < 16; nt++)
        #pragma unroll
        for (int q = 0; q < 4; q++) acc[nt][q] = 0.f;

    for (int ph = 0; ph < 2; ph++) {
        __syncthreads();
        {
            const uint4* wsrc = (const uint4*)(g_wfrag + (size_t)(3 + ph) * 131072);
            uint4* wdst = (uint4*)smem;
            #pragma unroll
            for (int i = 0; i < 32; i++) wdst[tid + i * 256] = wsrc[tid + i * 256];
        }
        __syncthreads();
        uint4 ah = *(const uint4*)(g_fragX[2 * ph] + ((size_t)(mt * 8) * 32 + lane) * 16);
        for (int ksl = 0; ksl < 16; ksl++) {
            uint4 nah;
            if (ksl < 15) {
                int gk = ph * 16 + ksl + 1;
                nah = *(const uint4*)(g_fragX[gk >> 3]
                        + ((size_t)(mt * 8 + (gk & 7)) * 32 + lane) * 16);
            }
            #pragma unroll
            for (int nt = 0; nt < 16; nt++) {
                uint4 b = ((const uint4*)smem)[(nt * 16 + ksl) * 32 + lane];
                mma_f16(acc[nt], ah, b.x, b.y);
                mma_f16(acc[nt], ah, b.z, b.w);
            }
            if (ksl < 15) ah = nah;
        }
    }

    bool w0 = m0 < (size_t)NNODES, w1 = m1 < (size_t)NNODES;
    #pragma unroll
    for (int nt = 0; nt < 16; nt++) {
        int n0 = nt * 8 + tg * 2;
        float b0 = s_bias[n0], b1 = s_bias[n0 + 1];
        if (w0) *(float2*)(outp + m0 * H + n0) = make_float2(acc[nt][0] + b0, acc[nt][1] + b1);
        if (w1) *(float2*)(outp + m1 * H + n0) = make_float2(acc[nt][2] + b0, acc[nt][3] + b1);
    }
}

// ---------------- launch ----------------
extern "C" void kernel_launch(void* const* d_in, const int* in_sizes, int n_in,
                              void* d_out, int out_size) {
    const float* emb = (const float*)d_in[0];
    const float* Wl  = (const float*)d_in[1];
    const float* bl  = (const float*)d_in[2];
    const float* Wr  = (const float*)d_in[3];
    const float* lg  = (const float*)d_in[4];
    const float* lb  = (const float*)d_in[5];
    const float* jkW = (const float*)d_in[6];
    const float* jkb = (const float*)d_in[7];
    const int*   ei  = (const int*)d_in[8];
    int E = in_sizes[8] / 2;
    const int* src = ei;
    const int* dst = ei + E;
    float* out = (float*)d_out;

    cudaFuncSetAttribute(k_mma, cudaFuncAttributeMaxDynamicSharedMemorySize, MMA_SMEM);
    cudaFuncSetAttribute(k_jk,  cudaFuncAttributeMaxDynamicSharedMemorySize, JK_SMEM);

    k_zero_deg<<<(NP + 255) / 256, 256>>>();
    k_hist<<<(E + 255) / 256, 256>>>(dst, E);
    k_scan1<<<NBLK, 1024>>>();
    k_scan2<<<1, 128>>>();
    k_scan3<<<(NP + 255) / 256, 256>>>();
    k_fill<<<(E + 255) / 256, 256>>>(src, dst, E);
    k_emb_frag<<<NT16, 256>>>(emb);
    k_conv_w<<<(5 * 16 * 16 * 32 + 255) / 256, 256>>>(Wl, Wr, jkW);

    for (int l = 0; l < 3; l++) {
        k_agg<<<NT16, 512>>>(l);
        k_mma<<<148, 256, MMA_SMEM>>>(l, bl + l * H, lg + l * H, lb + l * H);
    }
    k_jk<<<NTILE, 256, JK_SMEM>>>(jkb, out);
}

// round 17
// speedup vs baseline: 1.5069x; 1.1069x over previous
#include <cuda_runtime.h>
#include <cuda_fp16.h>
#include <cstdint>

#define NNODES 100000
#define NP     100352            // multiple of 1024 and 128
#define H      128
#define EMAX   1600000
#define NT16   (NP / 16)
#define NTILE  (NP / 128)        // 784 GEMM tiles
#define NBLK   (NP / 1024)       // 98 scan blocks

// ---------------- device scratch ----------------
__device__ __half g_Xh[3][(size_t)NP * H];     // fp16 X0..X2 (gather + residual source)
__device__ int    g_deg[NP];
__device__ float  g_invdeg[NP];
__device__ int    g_rowstart[NP + 1];
__device__ int    g_cursor[NP];
__device__ int    g_csrsrc[EMAX];
__device__ int    g_blocksum[NBLK];
// W fragments (fp16 hi/lo): tgt t (0..4): addr = t*131072 + ((nt*16 + ks)*32 + lane)*16
__device__ uint8_t g_wfrag[5 * 131072];
// A fragments (fp16): [tile][ks 0..7][lane]*16B
__device__ uint8_t g_fragAgg[(size_t)NT16 * 4096];
__device__ uint8_t g_fragX[4][(size_t)NT16 * 4096];

// ---------------- fp16 helpers ----------------
__device__ __forceinline__ uint32_t pack_h2(float v0, float v1) {
    __half2 h = __floats2half2_rn(v0, v1);
    return *(uint32_t*)&h;
}
__device__ __forceinline__ void hsplit2(float v0, float v1, uint32_t& ph, uint32_t& pl) {
    __half h0 = __float2half_rn(v0), h1 = __float2half_rn(v1);
    float r0 = v0 - __half2float(h0), r1 = v1 - __half2float(h1);
    __half l0 = __float2half_rn(r0), l1 = __float2half_rn(r1);
    ph = ((uint32_t)__half_as_ushort(h1) << 16) | (uint32_t)__half_as_ushort(h0);
    pl = ((uint32_t)__half_as_ushort(l1) << 16) | (uint32_t)__half_as_ushort(l0);
}

// ---------------- CSR build ----------------
__global__ void k_zero_deg() {
    int i = blockIdx.x * blockDim.x + threadIdx.x;
    if (i < NP) g_deg[i] = 0;
}
__global__ void k_hist(const int* __restrict__ dst, int E) {
    int i = blockIdx.x * blockDim.x + threadIdx.x;
    if (i < E) atomicAdd(&g_deg[dst[i]], 1);
}
__global__ void __launch_bounds__(1024) k_scan1() {
    __shared__ int wt[32];
    int t = threadIdx.x, lane = t & 31, wid = t >> 5;
    int i = blockIdx.x * 1024 + t;
    int v = g_deg[i];
    int x = v;
    #pragma unroll
    for (int d = 1; d < 32; d <<= 1) {
        int y = __shfl_up_sync(0xffffffffu, x, d);
        if (lane >= d) x += y;
    }
    if (lane == 31) wt[wid] = x;
    __syncthreads();
    if (wid == 0) {
        int y = wt[lane];
        #pragma unroll
        for (int d = 1; d < 32; d <<= 1) {
            int z = __shfl_up_sync(0xffffffffu, y, d);
            if (lane >= d) y += z;
        }
        wt[lane] = y;
    }
    __syncthreads();
    int off = (wid == 0) ? 0 : wt[wid - 1];
    g_rowstart[i] = off + x - v;
    if (t == 1023) g_blocksum[blockIdx.x] = off + x;
    g_invdeg[i] = 1.0f / fmaxf((float)v, 1.0f);
    g_cursor[i] = 0;
}
__global__ void k_scan2() {
    __shared__ int wt[4];
    int t = threadIdx.x, lane = t & 31, wid = t >> 5;
    int v = (t < NBLK) ? g_blocksum[t] : 0;
    int x = v;
    #pragma unroll
    for (int d = 1; d < 32; d <<= 1) {
        int y = __shfl_up_sync(0xffffffffu, x, d);
        if (lane >= d) x += y;
    }
    if (lane == 31) wt[wid] = x;
    __syncthreads();
    if (t == 0) {
        int r = 0;
        #pragma unroll
        for (int w = 0; w < 4; w++) { int tmp = wt[w]; wt[w] = r; r += tmp; }
        g_rowstart[NP] = r;
    }
    __syncthreads();
    if (t < NBLK) g_blocksum[t] = wt[wid] + x - v;
}
__global__ void k_scan3() {
    int i = blockIdx.x * blockDim.x + threadIdx.x;
    if (i < NP) g_rowstart[i] += g_blocksum[i >> 10];
}
__global__ void k_fill(const int* __restrict__ src, const int* __restrict__ dst, int E) {
    int i = blockIdx.x * blockDim.x + threadIdx.x;
    if (i < E) {
        int d = dst[i];
        int p = atomicAdd(&g_cursor[d], 1);
        g_csrsrc[g_rowstart[d] + p] = src[i];
    }
}

// ---------------- frag emit from smem tile (fp16 single) ----------------
#define SROW 132
__device__ __forceinline__ void tile_to_frag_h(const float* s_tile, uint8_t* fragdst,
                                               int tile, int cid) {
    int ks = cid >> 5, lane = cid & 31;
    int g = lane >> 2, tg = lane & 3;
    const float* rA = s_tile + g * SROW;
    const float* rB = s_tile + (g + 8) * SROW;
    int c = ks * 16 + tg * 2;
    uint4 a;
    a.x = pack_h2(rA[c], rA[c + 1]);
    a.y = pack_h2(rB[c], rB[c + 1]);
    a.z = pack_h2(rA[c + 8], rA[c + 9]);
    a.w = pack_h2(rB[c + 8], rB[c + 9]);
    *(uint4*)(fragdst + ((size_t)(tile * 8 + ks) * 32 + lane) * 16) = a;
}

// ---------------- emb: fp16 mirror + frag conversion (no float copy) ----------------
__global__ void __launch_bounds__(256) k_emb_frag(const float* __restrict__ emb) {
    __shared__ float s_tile[16 * SROW];
    int tid = threadIdx.x;
    int tile = blockIdx.x;
    size_t rowBase = (size_t)tile * 16;
    #pragma unroll
    for (int i = 0; i < 2; i++) {
        int idx = tid + i * 256;
        int r = idx >> 5, c4 = idx & 31;
        size_t row = rowBase + r;
        float4 v = make_float4(0.f, 0.f, 0.f, 0.f);
        if (row < (size_t)NNODES) v = ((const float4*)(emb + row * H))[c4];
        *(float4*)(s_tile + r * SROW + c4 * 4) = v;
        uint2 hp = make_uint2(pack_h2(v.x, v.y), pack_h2(v.z, v.w));
        ((uint2*)(g_Xh[0] + row * H))[c4] = hp;
    }
    __syncthreads();
    tile_to_frag_h(s_tile, g_fragX[0], tile, tid);
}

// ---------------- aggregation: warp/node, fp16 gather MLP=8, tile->frag ----------------
__device__ __forceinline__ void acc_h4(uint2 u, float& a0, float& a1, float& a2, float& a3) {
    float2 f01 = __half22float2(*(__half2*)&u.x);
    float2 f23 = __half22float2(*(__half2*)&u.y);
    a0 += f01.x; a1 += f01.y; a2 += f23.x; a3 += f23.y;
}
__global__ void __launch_bounds__(512) k_agg(int layer) {
    __shared__ float s_tile[16 * SROW];
    int tid = threadIdx.x, w = tid >> 5, lane = tid & 31;
    int tile = blockIdx.x;
    int node = tile * 16 + w;
    const __half* __restrict__ xin = g_Xh[layer];
    int s0 = g_rowstart[node], s1 = g_rowstart[node + 1];
    float ax = 0.f, ay = 0.f, az = 0.f, aw = 0.f;
    int j = s0;
    for (; j + 8 <= s1; j += 8) {
        int ix[8];
        #pragma unroll
        for (int q = 0; q < 8; q++) ix[q] = g_csrsrc[j + q];
        uint2 v[8];
        #pragma unroll
        for (int q = 0; q < 8; q++)
            v[q] = ((const uint2*)(xin + (size_t)ix[q] * H))[lane];
        #pragma unroll
        for (int q = 0; q < 8; q++) acc_h4(v[q], ax, ay, az, aw);
    }
    for (; j < s1; j++) {
        int i0 = g_csrsrc[j];
        uint2 a = ((const uint2*)(xin + (size_t)i0 * H))[lane];
        acc_h4(a, ax, ay, az, aw);
    }
    float inv = g_invdeg[node];
    *(float4*)(s_tile + w * SROW + lane * 4) = make_float4(ax * inv, ay * inv, az * inv, aw * inv);
    __syncthreads();
    if (tid < 256) tile_to_frag_h(s_tile, g_fragAgg, tile, tid);
}

// ---------------- W fragment build (fp16 hi/lo) ----------------
__global__ void k_conv_w(const float* __restrict__ Wl, const float* __restrict__ Wr,
                         const float* __restrict__ jkW) {
    int idx = blockIdx.x * blockDim.x + threadIdx.x;
    if (idx >= 5 * 16 * 16 * 32) return;
    int lane = idx & 31;
    int ks = (idx >> 5) & 15;
    int nt = (idx >> 9) & 15;
    int tgt = idx >> 13;
    int g = lane >> 2, tg = lane & 3;
    int n = nt * 8 + g;
    int k = ks * 16 + tg * 2;

    float v[4];
    if (tgt < 3) {
        #pragma unroll
        for (int q = 0; q < 4; q++) {
            int kk = k + (q >> 1) * 8 + (q & 1);
            v[q] = (kk < 128) ? Wl[(size_t)tgt * 16384 + n * 128 + kk]
                              : Wr[(size_t)tgt * 16384 + n * 128 + kk - 128];
        }
    } else {
        int h = tgt - 3;
        #pragma unroll
        for (int q = 0; q < 4; q++) {
            int kk = k + (q >> 1) * 8 + (q & 1);
            v[q] = jkW[(size_t)n * 512 + h * 256 + kk];
        }
    }
    uint32_t wh0, wl0, wh1, wl1;
    hsplit2(v[0], v[1], wh0, wl0);
    hsplit2(v[2], v[3], wh1, wl1);
    *(uint4*)(g_wfrag + (size_t)tgt * 131072 + ((size_t)((nt * 16 + ks) * 32 + lane)) * 16)
        = make_uint4(wh0, wh1, wl0, wl1);
}

// ---------------- mma helper (f16 kind) ----------------
__device__ __forceinline__ void mma_f16(float* c, uint4 a, uint32_t b0, uint32_t b1) {
    asm volatile(
        "mma.sync.aligned.m16n8k16.row.col.f32.f16.f16.f32 "
        "{%0,%1,%2,%3}, {%4,%5,%6,%7}, {%8,%9}, {%0,%1,%2,%3};"
        : "+f"(c[0]), "+f"(c[1]), "+f"(c[2]), "+f"(c[3])
        : "r"(a.x), "r"(a.y), "r"(a.z), "r"(a.w), "r"(b0), "r"(b1));
}

// ================= persistent layer GEMM (f16, residual from mirror, no float X) ==========
#define MMA_SMEM (131072 + 3 * 128 * 4)
__global__ void __launch_bounds__(256, 1) k_mma(
    int layer, const float* __restrict__ bias, const float* __restrict__ gamma,
    const float* __restrict__ beta)
{
    extern __shared__ uint8_t smem[];
    float* s_par = (float*)(smem + 131072);
    int tid = threadIdx.x, w = tid >> 5, lane = tid & 31;
    int g = lane >> 2, tg = lane & 3;

    if (tid < 128) {
        s_par[tid] = bias[tid];
        s_par[128 + tid] = gamma[tid];
        s_par[256 + tid] = beta[tid];
    }
    {
        const uint4* wsrc = (const uint4*)(g_wfrag + (size_t)layer * 131072);
        uint4* wdst = (uint4*)smem;
        #pragma unroll
        for (int i = 0; i < 32; i++) wdst[tid + i * 256] = wsrc[tid + i * 256];
    }
    __syncthreads();

    const uint8_t* fragXl = g_fragX[layer];
    const __half* xinh = g_Xh[layer];
    __half* xhout = (layer < 2) ? g_Xh[layer + 1] : (__half*)nullptr;
    uint8_t* fragout = g_fragX[layer + 1];
    bool wr_half = (layer < 2);

    for (int tb = blockIdx.x; tb < NTILE; tb += gridDim.x) {
        int mt = tb * 8 + w;
        size_t m0 = (size_t)mt * 16 + g, m1 = m0 + 8;

        float acc[16][4];
        #pragma unroll
        for (int nt = 0; nt < 16; nt++)
            #pragma unroll
            for (int q = 0; q < 4; q++) acc[nt][q] = 0.f;

        uint4 ah = *(const uint4*)(g_fragAgg + ((size_t)(mt * 8) * 32 + lane) * 16);
        for (int ksl = 0; ksl < 16; ksl++) {
            uint4 nah;
            if (ksl < 15) {
                int nk = ksl + 1;
                const uint8_t* asrc = (nk < 8) ? g_fragAgg : fragXl;
                nah = *(const uint4*)(asrc + ((size_t)(mt * 8 + (nk & 7)) * 32 + lane) * 16);
            }
            #pragma unroll
            for (int nt = 0; nt < 16; nt++) {
                uint4 b = ((const uint4*)smem)[(nt * 16 + ksl) * 32 + lane];
                mma_f16(acc[nt], ah, b.x, b.y);
                mma_f16(acc[nt], ah, b.z, b.w);
            }
            if (ksl < 15) ah = nah;
        }

        #pragma unroll
        for (int nt = 0; nt < 16; nt++) {
            int n0 = nt * 8 + tg * 2;
            float b0 = s_par[n0], b1 = s_par[n0 + 1];
            acc[nt][0] += b0; acc[nt][1] += b1;
            acc[nt][2] += b0; acc[nt][3] += b1;
        }
        float s0 = 0.f, q0 = 0.f, s1 = 0.f, q1 = 0.f;
        #pragma unroll
        for (int nt = 0; nt < 16; nt++) {
            s0 += acc[nt][0] + acc[nt][1];
            q0 += acc[nt][0] * acc[nt][0] + acc[nt][1] * acc[nt][1];
            s1 += acc[nt][2] + acc[nt][3];
            q1 += acc[nt][2] * acc[nt][2] + acc[nt][3] * acc[nt][3];
        }
        #pragma unroll
        for (int o = 1; o <= 2; o <<= 1) {
            s0 += __shfl_xor_sync(0xffffffffu, s0, o);
            q0 += __shfl_xor_sync(0xffffffffu, q0, o);
            s1 += __shfl_xor_sync(0xffffffffu, s1, o);
            q1 += __shfl_xor_sync(0xffffffffu, q1, o);
        }
        float mu0 = s0 * (1.0f / H), mu1 = s1 * (1.0f / H);
        float rs0 = rsqrtf(q0 * (1.0f / H) - mu0 * mu0 + 1e-5f);
        float rs1 = rsqrtf(q1 * (1.0f / H) - mu1 * mu1 + 1e-5f);

        #pragma unroll
        for (int ks2 = 0; ks2 < 8; ks2++) {
            float2 oa0, oa1, ob0, ob1;
            #pragma unroll
            for (int half = 0; half < 2; half++) {
                int nt = 2 * ks2 + half;
                int n0 = nt * 8 + tg * 2;
                float ga0 = s_par[128 + n0], ga1 = s_par[128 + n0 + 1];
                float be0 = s_par[256 + n0], be1 = s_par[256 + n0 + 1];
                float2 o0, o1;
                o0.x = fmaxf((acc[nt][0] - mu0) * rs0 * ga0 + be0, 0.f);
                o0.y = fmaxf((acc[nt][1] - mu0) * rs0 * ga1 + be1, 0.f);
                o1.x = fmaxf((acc[nt][2] - mu1) * rs1 * ga0 + be0, 0.f);
                o1.y = fmaxf((acc[nt][3] - mu1) * rs1 * ga1 + be1, 0.f);
                if (layer > 0) {
                    uint32_t r0 = *(const uint32_t*)(xinh + m0 * H + n0);
                    uint32_t r1 = *(const uint32_t*)(xinh + m1 * H + n0);
                    float2 f0 = __half22float2(*(__half2*)&r0);
                    float2 f1 = __half22float2(*(__half2*)&r1);
                    o0.x += f0.x; o0.y += f0.y;
                    o1.x += f1.x; o1.y += f1.y;
                }
                if (wr_half) {
                    *(uint32_t*)(xhout + m0 * H + n0) = pack_h2(o0.x, o0.y);
                    *(uint32_t*)(xhout + m1 * H + n0) = pack_h2(o1.x, o1.y);
                }
                if (half == 0) { oa0 = o0; oa1 = o1; }
                else           { ob0 = o0; ob1 = o1; }
            }
            uint4 fa;
            fa.x = pack_h2(oa0.x, oa0.y);
            fa.y = pack_h2(oa1.x, oa1.y);
            fa.z = pack_h2(ob0.x, ob0.y);
            fa.w = pack_h2(ob1.x, ob1.y);
            *(uint4*)(fragout + ((size_t)(mt * 8 + ks2) * 32 + lane) * 16) = fa;
        }
    }
}

// ================= JK (f16, 2 MMAs/chunk, A prefetch): 2 K=256 phases =================
#define JK_SMEM (131072 + 512)
__global__ void __launch_bounds__(256, 1) k_jk(
    const float* __restrict__ jkb, float* __restrict__ outp)
{
    extern __shared__ uint8_t smem[];
    float* s_bias = (float*)(smem + 131072);
    int tid = threadIdx.x, w = tid >> 5, lane = tid & 31;
    int g = lane >> 2, tg = lane & 3;
    int mt = blockIdx.x * 8 + w;
    size_t m0 = (size_t)mt * 16 + g, m1 = m0 + 8;

    if (tid < 128) s_bias[tid] = jkb[tid];

    float acc[16][4];
    #pragma unroll
    for (int nt = 0; nt < 16; nt++)
        #pragma unroll
        for (int q = 0; q < 4; q++) acc[nt][q] = 0.f;

    for (int ph = 0; ph < 2; ph++) {
        __syncthreads();
        {
            const uint4* wsrc = (const uint4*)(g_wfrag + (size_t)(3 + ph) * 131072);
            uint4* wdst = (uint4*)smem;
            #pragma unroll
            for (int i = 0; i < 32; i++) wdst[tid + i * 256] = wsrc[tid + i * 256];
        }
        __syncthreads();
        uint4 ah = *(const uint4*)(g_fragX[2 * ph] + ((size_t)(mt * 8) * 32 + lane) * 16);
        for (int ksl = 0; ksl < 16; ksl++) {
            uint4 nah;
            if (ksl < 15) {
                int gk = ph * 16 + ksl + 1;
                nah = *(const uint4*)(g_fragX[gk >> 3]
                        + ((size_t)(mt * 8 + (gk & 7)) * 32 + lane) * 16);
            }
            #pragma unroll
            for (int nt = 0; nt < 16; nt++) {
                uint4 b = ((const uint4*)smem)[(nt * 16 + ksl) * 32 + lane];
                mma_f16(acc[nt], ah, b.x, b.y);
                mma_f16(acc[nt], ah, b.z, b.w);
            }
            if (ksl < 15) ah = nah;
        }
    }

    bool w0 = m0 < (size_t)NNODES, w1 = m1 < (size_t)NNODES;
    #pragma unroll
    for (int nt = 0; nt < 16; nt++) {
        int n0 = nt * 8 + tg * 2;
        float b0 = s_bias[n0], b1 = s_bias[n0 + 1];
        if (w0) *(float2*)(outp + m0 * H + n0) = make_float2(acc[nt][0] + b0, acc[nt][1] + b1);
        if (w1) *(float2*)(outp + m1 * H + n0) = make_float2(acc[nt][2] + b0, acc[nt][3] + b1);
    }
}

// ---------------- launch ----------------
extern "C" void kernel_launch(void* const* d_in, const int* in_sizes, int n_in,
                              void* d_out, int out_size) {
    const float* emb = (const float*)d_in[0];
    const float* Wl  = (const float*)d_in[1];
    const float* bl  = (const float*)d_in[2];
    const float* Wr  = (const float*)d_in[3];
    const float* lg  = (const float*)d_in[4];
    const float* lb  = (const float*)d_in[5];
    const float* jkW = (const float*)d_in[6];
    const float* jkb = (const float*)d_in[7];
    const int*   ei  = (const int*)d_in[8];
    int E = in_sizes[8] / 2;
    const int* src = ei;
    const int* dst = ei + E;
    float* out = (float*)d_out;

    cudaFuncSetAttribute(k_mma, cudaFuncAttributeMaxDynamicSharedMemorySize, MMA_SMEM);
    cudaFuncSetAttribute(k_jk,  cudaFuncAttributeMaxDynamicSharedMemorySize, JK_SMEM);

    k_zero_deg<<<(NP + 255) / 256, 256>>>();
    k_hist<<<(E + 255) / 256, 256>>>(dst, E);
    k_scan1<<<NBLK, 1024>>>();
    k_scan2<<<1, 128>>>();
    k_scan3<<<(NP + 255) / 256, 256>>>();
    k_fill<<<(E + 255) / 256, 256>>>(src, dst, E);
    k_emb_frag<<<NT16, 256>>>(emb);
    k_conv_w<<<(5 * 16 * 16 * 32 + 255) / 256, 256>>>(Wl, Wr, jkW);

    for (int l = 0; l < 3; l++) {
        k_agg<<<NT16, 512>>>(l);
        k_mma<<<148, 256, MMA_SMEM>>>(l, bl + l * H, lg + l * H, lb + l * H);
    }
    k_jk<<<NTILE, 256, JK_SMEM>>>(jkb, out);
}